// round 12
// baseline (speedup 1.0000x reference)
#include <cuda_runtime.h>
#include <math.h>
#include <stdint.h>

// ============================================================================
// ProjectedAdaptiveLogSoftmax — fused adaptive softmax NLL (mean) on GB300
//
// Stages (all on one stream, graph-capturable, no allocations):
//   0. detect    : probe target dtype (int32 vs int64) -> g_is64 flag
//   1. init      : zero per-cluster row counters
//   2. classify  : compact row indices per tail cluster (atomics; result set
//                  is deterministic, per-row outputs are order-independent)
//   3. proj GEMM : P_i = hidden @ proj_i   (stored in __device__ scratch)
//   4. head GEMM : streaming (m, s) logsumexp partials over 20003 logits
//   5. reduce    : head LSE per row
//   6. sel       : the few individual logits needed (target col, cluster cols,
//                  tail target col) via one warp-dot per row
//   7. tail GEMMs: streaming LSE partials, gathered over compacted row lists
//   8. final     : per-row NLL, tree-reduced mean -> d_out[0]
// ============================================================================

#define NROWS   1024
#define DHID    1024
#define TM      128
#define TN      128
#define TK      8
#define PSTRIDE 1280   // >= ceil(160000/128) = 1250 partial blocks per row

#define CUT1 20000
#define CUT2 40000
#define CUT3 200000

// ------------------------- device scratch (static) -------------------------
static __device__ float g_P0[NROWS * 1024];
static __device__ float g_P1[NROWS * 256];
static __device__ float g_P2[NROWS * 64];
static __device__ float g_P3[NROWS * 16];
static __device__ float g_pm[NROWS * PSTRIDE];
static __device__ float g_ps[NROWS * PSTRIDE];
static __device__ float g_head_lse[NROWS];
static __device__ float g_tail_lse[NROWS];
static __device__ float g_sel_head[NROWS];
static __device__ float g_sel_cluster[NROWS];
static __device__ float g_sel_tail[NROWS];
static __device__ int   g_rows[3 * NROWS];
static __device__ int   g_cnt[3];
static __device__ int   g_is64;

// ------------------------------ helpers ------------------------------------
__device__ __forceinline__ int cluster_of(long long t) {
    return (t < CUT1) ? 0 : (t < CUT2) ? 1 : (t < CUT3) ? 2 : 3;
}

// dtype-agnostic target load (dispatches on runtime-detected width)
__device__ __forceinline__ long long ld_target(const void* p, int r) {
    if (g_is64) return ((const long long*)p)[r];
    return (long long)((const int*)p)[r];
}

// online logsumexp merge of (m1,s1) <- (m1,s1) + (m2,s2)
__device__ __forceinline__ void lse_combine(float& m, float& s, float m2, float s2) {
    float mn = fmaxf(m, m2);
    if (mn == -INFINITY) { m = mn; s = 0.f; return; }   // both empty
    s = s * __expf(m - mn) + s2 * __expf(m2 - mn);      // expf(-inf)=0, expf(0)=1
    m = mn;
}

// ---- dtype probe: view first 1024 int32 words (valid for either dtype).
// int64 targets (< 2^18) -> all 512 odd words are hi==0.
// int32 targets -> odd words are random values, ~surely nonzero somewhere.
__global__ void detect_kernel(const int* __restrict__ t32) {
    __shared__ int nz;
    if (threadIdx.x == 0) nz = 0;
    __syncthreads();
    for (int i = 2 * threadIdx.x + 1; i < NROWS; i += 2 * blockDim.x)
        if (t32[i] != 0) nz = 1;
    __syncthreads();
    if (threadIdx.x == 0) g_is64 = (nz == 0);
}

__global__ void init_kernel() {
    if (threadIdx.x < 3) g_cnt[threadIdx.x] = 0;
}

__global__ void classify_kernel(const void* __restrict__ target) {
    int r = blockIdx.x * blockDim.x + threadIdx.x;
    if (r >= NROWS) return;
    int c = cluster_of(ld_target(target, r));
    if (c > 0) {
        int p = atomicAdd(&g_cnt[c - 1], 1);
        g_rows[(c - 1) * NROWS + p] = r;
    }
}

// ============================================================================
// Tiled GEMM, fp32 with packed fma.rn.f32x2 (FFMA2) accumulation.
//   BNT  : B is [V, dK] row-major (weights; we need B^T)  vs [dK, V] (proj)
//   LSE  : emit per-(row, col-block) logsumexp partials    vs store C
//   HEAD : B is concat(W0[V0,dK], cluster_W[V-V0,dK]) with bias2 for tail cols
// Tile: 128x128 output, K-step 8, 256 threads, 8x8 micro-tile per thread.
// ============================================================================
template <bool BNT, bool LSE, bool HEAD>
__global__ __launch_bounds__(256, 2)
void gemm_kernel(const float* __restrict__ A, int dK,
                 const float* __restrict__ B, const float* __restrict__ B2,
                 const float* __restrict__ bias, const float* __restrict__ bias2,
                 int V, int V0,
                 float* __restrict__ C, int ldc,
                 const int* __restrict__ rowlist, const int* __restrict__ cntptr,
                 float* __restrict__ pm, float* __restrict__ ps)
{
    const int cnt  = cntptr ? *cntptr : NROWS;
    const int row0 = blockIdx.y * TM;
    if (rowlist && row0 >= cnt) return;           // dead row tile (tail clusters)
    const int col0 = blockIdx.x * TN;

    __shared__ int   rid[TM];
    __shared__ float As[TK][TM];
    __shared__ float Bs[TK][TN];

    const int tid = threadIdx.x;
    const int tx  = tid & 15;
    const int ty  = tid >> 4;

    if (tid < TM) {
        int pos  = row0 + tid;
        rid[tid] = rowlist ? (pos < cnt ? rowlist[pos] : 0) : pos;
    }

    // packed f32x2 accumulators: acc[i][j] holds cols (2j, 2j+1) of row i
    unsigned long long acc[8][4];
#pragma unroll
    for (int i = 0; i < 8; i++)
#pragma unroll
        for (int j = 0; j < 4; j++) acc[i][j] = 0ull;

    // per-thread load coords
    const int am = tid >> 1;            // 0..127 (row within tile)
    const int ak = (tid & 1) * 4;       // 0 or 4 (k within TK)
    const int pk = tid >> 5;            // proj-mode: k within TK (0..7)
    const int pn = (tid & 31) * 4;      // proj-mode: col within tile

    for (int k0 = 0; k0 < dK; k0 += TK) {
        __syncthreads();   // protect smem from previous iteration's readers (and rid)

        // ---- load A tile: As[k][m] = A[rid[m]][k0+k]
        {
            const float4 v = *(const float4*)(A + (size_t)rid[am] * dK + k0 + ak);
            As[ak + 0][am] = v.x; As[ak + 1][am] = v.y;
            As[ak + 2][am] = v.z; As[ak + 3][am] = v.w;
        }
        // ---- load B tile
        if (BNT) {          // Bs[k][n] = W[col0+n][k0+k]
            int cg = col0 + am;
            float4 v = make_float4(0.f, 0.f, 0.f, 0.f);
            if (HEAD) {
                if (cg < V0)      v = *(const float4*)(B  + (size_t)cg * dK + k0 + ak);
                else if (cg < V)  v = *(const float4*)(B2 + (size_t)(cg - V0) * dK + k0 + ak);
            } else {
                if (cg < V)       v = *(const float4*)(B  + (size_t)cg * dK + k0 + ak);
            }
            Bs[ak + 0][am] = v.x; Bs[ak + 1][am] = v.y;
            Bs[ak + 2][am] = v.z; Bs[ak + 3][am] = v.w;
        } else {            // Bs[k][n] = proj[k0+k][col0+n]  (contiguous in n)
            int cg = col0 + pn;
            float4 v = make_float4(0.f, 0.f, 0.f, 0.f);
            if (cg < V)  // V is a multiple of 4 for all projections
                v = *(const float4*)(B + (size_t)(k0 + pk) * V + cg);
            *(float4*)&Bs[pk][pn] = v;
        }
        __syncthreads();

        // ---- compute: 8x8 micro-tile, 32 FFMA2 per k
#pragma unroll
        for (int k = 0; k < TK; k++) {
            float a[8], b[8];
            *(float4*)(a)     = *(const float4*)&As[k][ty * 8];
            *(float4*)(a + 4) = *(const float4*)&As[k][ty * 8 + 4];
            *(float4*)(b)     = *(const float4*)&Bs[k][tx * 8];
            *(float4*)(b + 4) = *(const float4*)&Bs[k][tx * 8 + 4];

            unsigned long long av[8], bv[4];
#pragma unroll
            for (int i = 0; i < 8; i++)
                asm("mov.b64 %0, {%1, %1};" : "=l"(av[i]) : "f"(a[i]));
#pragma unroll
            for (int j = 0; j < 4; j++)
                asm("mov.b64 %0, {%1, %2};" : "=l"(bv[j]) : "f"(b[2 * j]), "f"(b[2 * j + 1]));
#pragma unroll
            for (int i = 0; i < 8; i++)
#pragma unroll
                for (int j = 0; j < 4; j++)
                    asm("fma.rn.f32x2 %0, %1, %2, %0;"
                        : "+l"(acc[i][j]) : "l"(av[i]), "l"(bv[j]));
        }
    }

    // unpack accumulators
    float accf[8][8];
#pragma unroll
    for (int i = 0; i < 8; i++)
#pragma unroll
        for (int j = 0; j < 4; j++)
            asm("mov.b64 {%0, %1}, %2;"
                : "=f"(accf[i][2 * j]), "=f"(accf[i][2 * j + 1]) : "l"(acc[i][j]));

    if (!LSE) {
        // store C (projection results); rows are identity here
#pragma unroll
        for (int i = 0; i < 8; i++) {
            int r = rid[ty * 8 + i];
#pragma unroll
            for (int j = 0; j < 8; j++) {
                int cg = col0 + tx * 8 + j;
                if (cg < V) C[(size_t)r * ldc + cg] = accf[i][j];
            }
        }
    } else {
        // add bias, mask OOB cols to -inf, per-row (m,s) over the 128-col tile
        const int cbase = col0 + tx * 8;
        float bj[8];
#pragma unroll
        for (int j = 0; j < 8; j++) {
            int cg = cbase + j;
            float bb = 0.f;
            if (cg < V) bb = (HEAD && cg >= V0) ? bias2[cg - V0] : bias[cg];
            bj[j] = bb;
        }
#pragma unroll
        for (int i = 0; i < 8; i++) {
            float m = -INFINITY;
            float v[8];
#pragma unroll
            for (int j = 0; j < 8; j++) {
                int cg = cbase + j;
                v[j] = (cg < V) ? (accf[i][j] + bj[j]) : -INFINITY;
                m = fmaxf(m, v[j]);
            }
            float s = 0.f;
            if (m > -INFINITY) {
#pragma unroll
                for (int j = 0; j < 8; j++) s += __expf(v[j] - m);
            }
            // reduce across the 16 lanes owning this row (xor<16 stays in group)
#pragma unroll
            for (int off = 8; off; off >>= 1) {
                float mo = __shfl_xor_sync(0xffffffffu, m, off);
                float so = __shfl_xor_sync(0xffffffffu, s, off);
                lse_combine(m, s, mo, so);
            }
            if (tx == 0) {
                int pidx = row0 + ty * 8 + i;   // list position (== row when identity)
                pm[(size_t)pidx * PSTRIDE + blockIdx.x] = m;
                ps[(size_t)pidx * PSTRIDE + blockIdx.x] = s;
            }
        }
    }
}

// ---------------- merge LSE partials per row --------------------------------
__global__ void reduce_lse_kernel(const float* __restrict__ pm, const float* __restrict__ ps,
                                  int nblk, float* __restrict__ out,
                                  const int* __restrict__ rowlist, const int* __restrict__ cntptr)
{
    int idx = blockIdx.x;
    if (cntptr && idx >= *cntptr) return;
    int tid = threadIdx.x;
    float m = -INFINITY, s = 0.f;
    for (int b = tid; b < nblk; b += 128)
        lse_combine(m, s, pm[(size_t)idx * PSTRIDE + b], ps[(size_t)idx * PSTRIDE + b]);
    __shared__ float sm[128], ss[128];
    sm[tid] = m; ss[tid] = s;
    __syncthreads();
    for (int off = 64; off; off >>= 1) {
        if (tid < off) {
            float mm = sm[tid], sv = ss[tid];
            lse_combine(mm, sv, sm[tid + off], ss[tid + off]);
            sm[tid] = mm; ss[tid] = sv;
        }
        __syncthreads();
    }
    if (tid == 0) {
        int row = rowlist ? rowlist[idx] : idx;
        out[row] = sm[0] + logf(ss[0]);
    }
}

// ---------------- selected logits: one warp per row --------------------------
__global__ void sel_kernel(const void* __restrict__ target,
                           const float* __restrict__ W0, const float* __restrict__ b0,
                           const float* __restrict__ W1, const float* __restrict__ b1,
                           const float* __restrict__ W2, const float* __restrict__ b2,
                           const float* __restrict__ W3, const float* __restrict__ b3,
                           const float* __restrict__ cW, const float* __restrict__ cb)
{
    int gw   = (blockIdx.x * blockDim.x + threadIdx.x) >> 5;
    int lane = threadIdx.x & 31;
    if (gw >= NROWS) return;
    long long t = ld_target(target, gw);
    int c = cluster_of(t);
    const float* p0 = g_P0 + (size_t)gw * 1024;

    // head token logit (t0 = clip(target, 0, 19999))
    {
        int colh = (int)(t < CUT1 ? t : (long long)(CUT1 - 1));
        const float* w = W0 + (size_t)colh * 1024;
        float acc = 0.f;
        for (int k = lane; k < 1024; k += 32) acc = fmaf(p0[k], w[k], acc);
#pragma unroll
        for (int o = 16; o; o >>= 1) acc += __shfl_xor_sync(0xffffffffu, acc, o);
        if (lane == 0) g_sel_head[gw] = acc + b0[colh];
    }
    if (c > 0) {
        // head cluster column: head_lp[:, -c] -> concat col (20003 - c) -> cluster_W[3-c]
        {
            const float* w = cW + (size_t)(3 - c) * 1024;
            float acc = 0.f;
            for (int k = lane; k < 1024; k += 32) acc = fmaf(p0[k], w[k], acc);
#pragma unroll
            for (int o = 16; o; o >>= 1) acc += __shfl_xor_sync(0xffffffffu, acc, o);
            if (lane == 0) g_sel_cluster[gw] = acc + cb[3 - c];
        }
        // tail token logit
        int lo = (c == 1) ? CUT1 : (c == 2) ? CUT2 : CUT3;
        int d  = (c == 1) ? 256  : (c == 2) ? 64   : 16;
        const float* P = (c == 1) ? g_P1 : (c == 2) ? g_P2 : g_P3;
        const float* W = (c == 1) ? W1 : (c == 2) ? W2 : W3;
        const float* B = (c == 1) ? b1 : (c == 2) ? b2 : b3;
        int ti = (int)(t - lo);
        const float* pr = P + (size_t)gw * d;
        const float* wr = W + (size_t)ti * d;
        float acc = 0.f;
        for (int k = lane; k < d; k += 32) acc = fmaf(pr[k], wr[k], acc);
#pragma unroll
        for (int o = 16; o; o >>= 1) acc += __shfl_xor_sync(0xffffffffu, acc, o);
        if (lane == 0) g_sel_tail[gw] = acc + B[ti];
    }
}

// ---------------- final NLL + mean -------------------------------------------
__global__ void final_kernel(const void* __restrict__ target, float* __restrict__ out)
{
    __shared__ float sh[NROWS];
    int r = threadIdx.x;
    int c = cluster_of(ld_target(target, r));
    float nll;
    if (c == 0)
        nll = g_head_lse[r] - g_sel_head[r];
    else
        nll = (g_head_lse[r] - g_sel_cluster[r]) + (g_tail_lse[r] - g_sel_tail[r]);
    sh[r] = nll;
    __syncthreads();
    for (int off = 512; off; off >>= 1) {
        if (r < off) sh[r] += sh[r + off];
        __syncthreads();
    }
    if (r == 0) out[0] = sh[0] * (1.0f / NROWS);
}

// ============================================================================
// launch
// ============================================================================
extern "C" void kernel_launch(void* const* d_in, const int* in_sizes, int n_in,
                              void* d_out, int out_size)
{
    const float* hidden = (const float*)d_in[0];
    const void*  target = d_in[1];                 // int32 or int64; detected on device
    const float* W0 = (const float*)d_in[2];
    const float* b0 = (const float*)d_in[3];
    const float* proj0 = (const float*)d_in[4];
    const float* W1 = (const float*)d_in[5];
    const float* b1 = (const float*)d_in[6];
    const float* proj1 = (const float*)d_in[7];
    const float* W2 = (const float*)d_in[8];
    const float* b2 = (const float*)d_in[9];
    const float* proj2 = (const float*)d_in[10];
    const float* W3 = (const float*)d_in[11];
    const float* b3 = (const float*)d_in[12];
    const float* proj3 = (const float*)d_in[13];
    const float* cW = (const float*)d_in[14];
    const float* cb = (const float*)d_in[15];
    float* out = (float*)d_out;

    void *vp0, *vp1, *vp2, *vp3, *vpm, *vps, *vhl, *vtl, *vrows, *vcnt;
    cudaGetSymbolAddress(&vp0, g_P0);
    cudaGetSymbolAddress(&vp1, g_P1);
    cudaGetSymbolAddress(&vp2, g_P2);
    cudaGetSymbolAddress(&vp3, g_P3);
    cudaGetSymbolAddress(&vpm, g_pm);
    cudaGetSymbolAddress(&vps, g_ps);
    cudaGetSymbolAddress(&vhl, g_head_lse);
    cudaGetSymbolAddress(&vtl, g_tail_lse);
    cudaGetSymbolAddress(&vrows, g_rows);
    cudaGetSymbolAddress(&vcnt, g_cnt);
    float* P0 = (float*)vp0;  float* P1 = (float*)vp1;
    float* P2 = (float*)vp2;  float* P3 = (float*)vp3;
    float* pm = (float*)vpm;  float* ps = (float*)vps;
    float* head_lse = (float*)vhl;  float* tail_lse = (float*)vtl;
    int* rows = (int*)vrows;  int* cnt = (int*)vcnt;

    detect_kernel<<<1, 256>>>((const int*)target);
    init_kernel<<<1, 32>>>();
    classify_kernel<<<4, 256>>>(target);

    // projections: P_i = hidden[1024,1024] @ proj_i[1024, d_i]
    gemm_kernel<false, false, false><<<dim3(8, 8), 256>>>(hidden, 1024, proj0, nullptr,
        nullptr, nullptr, 1024, 0, P0, 1024, nullptr, nullptr, nullptr, nullptr);
    gemm_kernel<false, false, false><<<dim3(2, 8), 256>>>(hidden, 1024, proj1, nullptr,
        nullptr, nullptr, 256, 0, P1, 256, nullptr, nullptr, nullptr, nullptr);
    gemm_kernel<false, false, false><<<dim3(1, 8), 256>>>(hidden, 1024, proj2, nullptr,
        nullptr, nullptr, 64, 0, P2, 64, nullptr, nullptr, nullptr, nullptr);
    gemm_kernel<false, false, false><<<dim3(1, 8), 256>>>(hidden, 1024, proj3, nullptr,
        nullptr, nullptr, 16, 0, P3, 16, nullptr, nullptr, nullptr, nullptr);

    // head: 20003 logits per row -> streaming LSE partials
    const int nblk_head = (20003 + TN - 1) / TN;   // 157
    gemm_kernel<true, true, true><<<dim3(nblk_head, 8), 256>>>(P0, 1024, W0, cW, b0, cb,
        20003, 20000, nullptr, 0, nullptr, nullptr, pm, ps);
    reduce_lse_kernel<<<NROWS, 128>>>(pm, ps, nblk_head, head_lse, nullptr, nullptr);

    // individual logits (target col / cluster cols / tail target col)
    sel_kernel<<<128, 256>>>(target, W0, b0, W1, b1, W2, b2, W3, b3, cW, cb);

    // tail cluster 1: V=20000, d=256
    {
        const int nblk = (20000 + TN - 1) / TN;    // 157
        gemm_kernel<true, true, false><<<dim3(nblk, 8), 256>>>(P1, 256, W1, nullptr, b1,
            nullptr, 20000, 0, nullptr, 0, rows + 0 * NROWS, cnt + 0, pm, ps);
        reduce_lse_kernel<<<NROWS, 128>>>(pm, ps, nblk, tail_lse, rows + 0 * NROWS, cnt + 0);
    }
    // tail cluster 2: V=160000, d=64
    {
        const int nblk = (160000 + TN - 1) / TN;   // 1250
        gemm_kernel<true, true, false><<<dim3(nblk, 8), 256>>>(P2, 64, W2, nullptr, b2,
            nullptr, 160000, 0, nullptr, 0, rows + 1 * NROWS, cnt + 1, pm, ps);
        reduce_lse_kernel<<<NROWS, 128>>>(pm, ps, nblk, tail_lse, rows + 1 * NROWS, cnt + 1);
    }
    // tail cluster 3: V=67735, d=16
    {
        const int nblk = (67735 + TN - 1) / TN;    // 530
        gemm_kernel<true, true, false><<<dim3(nblk, 8), 256>>>(P3, 16, W3, nullptr, b3,
            nullptr, 67735, 0, nullptr, 0, rows + 2 * NROWS, cnt + 2, pm, ps);
        reduce_lse_kernel<<<NROWS, 128>>>(pm, ps, nblk, tail_lse, rows + 2 * NROWS, cnt + 2);
    }

    final_kernel<<<1, NROWS>>>(target, out);
    (void)in_sizes; (void)n_in; (void)out_size;
}

// round 13
// speedup vs baseline: 1.0006x; 1.0006x over previous
#include <cuda_runtime.h>
#include <math.h>
#include <stdint.h>

// ============================================================================
// ProjectedAdaptiveLogSoftmax — fused adaptive softmax NLL (mean) on GB300
//
// Stages (all on one stream, graph-capturable, no allocations):
//   0. detect    : probe target dtype (int32 vs int64) -> g_is64 flag
//   1. init      : zero per-cluster row counters
//   2. classify  : compact row indices per tail cluster (atomics; result set
//                  is deterministic, per-row outputs are order-independent)
//   3. proj GEMM : P_i = hidden @ proj_i   (stored in __device__ scratch)
//   4. head GEMM : streaming (m, s) logsumexp partials over 20003 logits
//   5. reduce    : head LSE per row
//   6. sel       : the few individual logits needed (target col, cluster cols,
//                  tail target col) via one warp-dot per row
//   7. tail GEMMs: streaming LSE partials, gathered over compacted row lists
//   8. final     : per-row NLL, tree-reduced mean -> d_out[0]
// ============================================================================

#define NROWS   1024
#define DHID    1024
#define TM      128
#define TN      128
#define TK      8
#define PSTRIDE 1280   // >= ceil(160000/128) = 1250 partial blocks per row

#define CUT1 20000
#define CUT2 40000
#define CUT3 200000

// ------------------------- device scratch (static) -------------------------
static __device__ float g_P0[NROWS * 1024];
static __device__ float g_P1[NROWS * 256];
static __device__ float g_P2[NROWS * 64];
static __device__ float g_P3[NROWS * 16];
static __device__ float g_pm[NROWS * PSTRIDE];
static __device__ float g_ps[NROWS * PSTRIDE];
static __device__ float g_head_lse[NROWS];
static __device__ float g_tail_lse[NROWS];
static __device__ float g_sel_head[NROWS];
static __device__ float g_sel_cluster[NROWS];
static __device__ float g_sel_tail[NROWS];
static __device__ int   g_rows[3 * NROWS];
static __device__ int   g_cnt[3];
static __device__ int   g_is64;

// ------------------------------ helpers ------------------------------------
__device__ __forceinline__ int cluster_of(long long t) {
    return (t < CUT1) ? 0 : (t < CUT2) ? 1 : (t < CUT3) ? 2 : 3;
}

// dtype-agnostic target load (dispatches on runtime-detected width)
__device__ __forceinline__ long long ld_target(const void* p, int r) {
    if (g_is64) return ((const long long*)p)[r];
    return (long long)((const int*)p)[r];
}

// online logsumexp merge of (m1,s1) <- (m1,s1) + (m2,s2)
__device__ __forceinline__ void lse_combine(float& m, float& s, float m2, float s2) {
    float mn = fmaxf(m, m2);
    if (mn == -INFINITY) { m = mn; s = 0.f; return; }   // both empty
    s = s * __expf(m - mn) + s2 * __expf(m2 - mn);      // expf(-inf)=0, expf(0)=1
    m = mn;
}

// ---- dtype probe: view first 1024 int32 words (valid for either dtype).
// int64 targets (< 2^18) -> all 512 odd words are hi==0.
// int32 targets -> odd words are random values, ~surely nonzero somewhere.
__global__ void detect_kernel(const int* __restrict__ t32) {
    __shared__ int nz;
    if (threadIdx.x == 0) nz = 0;
    __syncthreads();
    for (int i = 2 * threadIdx.x + 1; i < NROWS; i += 2 * blockDim.x)
        if (t32[i] != 0) nz = 1;
    __syncthreads();
    if (threadIdx.x == 0) g_is64 = (nz == 0);
}

__global__ void init_kernel() {
    if (threadIdx.x < 3) g_cnt[threadIdx.x] = 0;
}

__global__ void classify_kernel(const void* __restrict__ target) {
    int r = blockIdx.x * blockDim.x + threadIdx.x;
    if (r >= NROWS) return;
    int c = cluster_of(ld_target(target, r));
    if (c > 0) {
        int p = atomicAdd(&g_cnt[c - 1], 1);
        g_rows[(c - 1) * NROWS + p] = r;
    }
}

// ============================================================================
// Tiled GEMM, fp32 with packed fma.rn.f32x2 (FFMA2) accumulation.
//   BNT  : B is [V, dK] row-major (weights; we need B^T)  vs [dK, V] (proj)
//   LSE  : emit per-(row, col-block) logsumexp partials    vs store C
//   HEAD : B is concat(W0[V0,dK], cluster_W[V-V0,dK]) with bias2 for tail cols
// Tile: 128x128 output, K-step 8, 256 threads, 8x8 micro-tile per thread.
// ============================================================================
template <bool BNT, bool LSE, bool HEAD>
__global__ __launch_bounds__(256, 2)
void gemm_kernel(const float* __restrict__ A, int dK,
                 const float* __restrict__ B, const float* __restrict__ B2,
                 const float* __restrict__ bias, const float* __restrict__ bias2,
                 int V, int V0,
                 float* __restrict__ C, int ldc,
                 const int* __restrict__ rowlist, const int* __restrict__ cntptr,
                 float* __restrict__ pm, float* __restrict__ ps)
{
    const int cnt  = cntptr ? *cntptr : NROWS;
    const int row0 = blockIdx.y * TM;
    if (rowlist && row0 >= cnt) return;           // dead row tile (tail clusters)
    const int col0 = blockIdx.x * TN;

    __shared__ int   rid[TM];
    __shared__ float As[TK][TM];
    __shared__ float Bs[TK][TN];

    const int tid = threadIdx.x;
    const int tx  = tid & 15;
    const int ty  = tid >> 4;

    if (tid < TM) {
        int pos  = row0 + tid;
        rid[tid] = rowlist ? (pos < cnt ? rowlist[pos] : 0) : pos;
    }

    // packed f32x2 accumulators: acc[i][j] holds cols (2j, 2j+1) of row i
    unsigned long long acc[8][4];
#pragma unroll
    for (int i = 0; i < 8; i++)
#pragma unroll
        for (int j = 0; j < 4; j++) acc[i][j] = 0ull;

    // per-thread load coords
    const int am = tid >> 1;            // 0..127 (row within tile)
    const int ak = (tid & 1) * 4;       // 0 or 4 (k within TK)
    const int pk = tid >> 5;            // proj-mode: k within TK (0..7)
    const int pn = (tid & 31) * 4;      // proj-mode: col within tile

    for (int k0 = 0; k0 < dK; k0 += TK) {
        __syncthreads();   // protect smem from previous iteration's readers (and rid)

        // ---- load A tile: As[k][m] = A[rid[m]][k0+k]
        {
            const float4 v = *(const float4*)(A + (size_t)rid[am] * dK + k0 + ak);
            As[ak + 0][am] = v.x; As[ak + 1][am] = v.y;
            As[ak + 2][am] = v.z; As[ak + 3][am] = v.w;
        }
        // ---- load B tile
        if (BNT) {          // Bs[k][n] = W[col0+n][k0+k]
            int cg = col0 + am;
            float4 v = make_float4(0.f, 0.f, 0.f, 0.f);
            if (HEAD) {
                if (cg < V0)      v = *(const float4*)(B  + (size_t)cg * dK + k0 + ak);
                else if (cg < V)  v = *(const float4*)(B2 + (size_t)(cg - V0) * dK + k0 + ak);
            } else {
                if (cg < V)       v = *(const float4*)(B  + (size_t)cg * dK + k0 + ak);
            }
            Bs[ak + 0][am] = v.x; Bs[ak + 1][am] = v.y;
            Bs[ak + 2][am] = v.z; Bs[ak + 3][am] = v.w;
        } else {            // Bs[k][n] = proj[k0+k][col0+n]  (contiguous in n)
            int cg = col0 + pn;
            float4 v = make_float4(0.f, 0.f, 0.f, 0.f);
            if (cg < V)  // V is a multiple of 4 for all projections
                v = *(const float4*)(B + (size_t)(k0 + pk) * V + cg);
            *(float4*)&Bs[pk][pn] = v;
        }
        __syncthreads();

        // ---- compute: 8x8 micro-tile, 32 FFMA2 per k
#pragma unroll
        for (int k = 0; k < TK; k++) {
            float a[8], b[8];
            *(float4*)(a)     = *(const float4*)&As[k][ty * 8];
            *(float4*)(a + 4) = *(const float4*)&As[k][ty * 8 + 4];
            *(float4*)(b)     = *(const float4*)&Bs[k][tx * 8];
            *(float4*)(b + 4) = *(const float4*)&Bs[k][tx * 8 + 4];

            unsigned long long av[8], bv[4];
#pragma unroll
            for (int i = 0; i < 8; i++)
                asm("mov.b64 %0, {%1, %1};" : "=l"(av[i]) : "f"(a[i]));
#pragma unroll
            for (int j = 0; j < 4; j++)
                asm("mov.b64 %0, {%1, %2};" : "=l"(bv[j]) : "f"(b[2 * j]), "f"(b[2 * j + 1]));
#pragma unroll
            for (int i = 0; i < 8; i++)
#pragma unroll
                for (int j = 0; j < 4; j++)
                    asm("fma.rn.f32x2 %0, %1, %2, %0;"
                        : "+l"(acc[i][j]) : "l"(av[i]), "l"(bv[j]));
        }
    }

    // unpack accumulators
    float accf[8][8];
#pragma unroll
    for (int i = 0; i < 8; i++)
#pragma unroll
        for (int j = 0; j < 4; j++)
            asm("mov.b64 {%0, %1}, %2;"
                : "=f"(accf[i][2 * j]), "=f"(accf[i][2 * j + 1]) : "l"(acc[i][j]));

    if (!LSE) {
        // store C (projection results); rows are identity here
#pragma unroll
        for (int i = 0; i < 8; i++) {
            int r = rid[ty * 8 + i];
#pragma unroll
            for (int j = 0; j < 8; j++) {
                int cg = col0 + tx * 8 + j;
                if (cg < V) C[(size_t)r * ldc + cg] = accf[i][j];
            }
        }
    } else {
        // add bias, mask OOB cols to -inf, per-row (m,s) over the 128-col tile
        const int cbase = col0 + tx * 8;
        float bj[8];
#pragma unroll
        for (int j = 0; j < 8; j++) {
            int cg = cbase + j;
            float bb = 0.f;
            if (cg < V) bb = (HEAD && cg >= V0) ? bias2[cg - V0] : bias[cg];
            bj[j] = bb;
        }
#pragma unroll
        for (int i = 0; i < 8; i++) {
            float m = -INFINITY;
            float v[8];
#pragma unroll
            for (int j = 0; j < 8; j++) {
                int cg = cbase + j;
                v[j] = (cg < V) ? (accf[i][j] + bj[j]) : -INFINITY;
                m = fmaxf(m, v[j]);
            }
            float s = 0.f;
            if (m > -INFINITY) {
#pragma unroll
                for (int j = 0; j < 8; j++) s += __expf(v[j] - m);
            }
            // reduce across the 16 lanes owning this row (xor<16 stays in group)
#pragma unroll
            for (int off = 8; off; off >>= 1) {
                float mo = __shfl_xor_sync(0xffffffffu, m, off);
                float so = __shfl_xor_sync(0xffffffffu, s, off);
                lse_combine(m, s, mo, so);
            }
            if (tx == 0) {
                int pidx = row0 + ty * 8 + i;   // list position (== row when identity)
                pm[(size_t)pidx * PSTRIDE + blockIdx.x] = m;
                ps[(size_t)pidx * PSTRIDE + blockIdx.x] = s;
            }
        }
    }
}

// ---------------- merge LSE partials per row --------------------------------
__global__ void reduce_lse_kernel(const float* __restrict__ pm, const float* __restrict__ ps,
                                  int nblk, float* __restrict__ out,
                                  const int* __restrict__ rowlist, const int* __restrict__ cntptr)
{
    int idx = blockIdx.x;
    if (cntptr && idx >= *cntptr) return;
    int tid = threadIdx.x;
    float m = -INFINITY, s = 0.f;
    for (int b = tid; b < nblk; b += 128)
        lse_combine(m, s, pm[(size_t)idx * PSTRIDE + b], ps[(size_t)idx * PSTRIDE + b]);
    __shared__ float sm[128], ss[128];
    sm[tid] = m; ss[tid] = s;
    __syncthreads();
    for (int off = 64; off; off >>= 1) {
        if (tid < off) {
            float mm = sm[tid], sv = ss[tid];
            lse_combine(mm, sv, sm[tid + off], ss[tid + off]);
            sm[tid] = mm; ss[tid] = sv;
        }
        __syncthreads();
    }
    if (tid == 0) {
        int row = rowlist ? rowlist[idx] : idx;
        out[row] = sm[0] + logf(ss[0]);
    }
}

// ---------------- selected logits: one warp per row --------------------------
__global__ void sel_kernel(const void* __restrict__ target,
                           const float* __restrict__ W0, const float* __restrict__ b0,
                           const float* __restrict__ W1, const float* __restrict__ b1,
                           const float* __restrict__ W2, const float* __restrict__ b2,
                           const float* __restrict__ W3, const float* __restrict__ b3,
                           const float* __restrict__ cW, const float* __restrict__ cb)
{
    int gw   = (blockIdx.x * blockDim.x + threadIdx.x) >> 5;
    int lane = threadIdx.x & 31;
    if (gw >= NROWS) return;
    long long t = ld_target(target, gw);
    int c = cluster_of(t);
    const float* p0 = g_P0 + (size_t)gw * 1024;

    // head token logit (t0 = clip(target, 0, 19999))
    {
        int colh = (int)(t < CUT1 ? t : (long long)(CUT1 - 1));
        const float* w = W0 + (size_t)colh * 1024;
        float acc = 0.f;
        for (int k = lane; k < 1024; k += 32) acc = fmaf(p0[k], w[k], acc);
#pragma unroll
        for (int o = 16; o; o >>= 1) acc += __shfl_xor_sync(0xffffffffu, acc, o);
        if (lane == 0) g_sel_head[gw] = acc + b0[colh];
    }
    if (c > 0) {
        // head cluster column: head_lp[:, -c] -> concat col (20003 - c) -> cluster_W[3-c]
        {
            const float* w = cW + (size_t)(3 - c) * 1024;
            float acc = 0.f;
            for (int k = lane; k < 1024; k += 32) acc = fmaf(p0[k], w[k], acc);
#pragma unroll
            for (int o = 16; o; o >>= 1) acc += __shfl_xor_sync(0xffffffffu, acc, o);
            if (lane == 0) g_sel_cluster[gw] = acc + cb[3 - c];
        }
        // tail token logit
        int lo = (c == 1) ? CUT1 : (c == 2) ? CUT2 : CUT3;
        int d  = (c == 1) ? 256  : (c == 2) ? 64   : 16;
        const float* P = (c == 1) ? g_P1 : (c == 2) ? g_P2 : g_P3;
        const float* W = (c == 1) ? W1 : (c == 2) ? W2 : W3;
        const float* B = (c == 1) ? b1 : (c == 2) ? b2 : b3;
        int ti = (int)(t - lo);
        const float* pr = P + (size_t)gw * d;
        const float* wr = W + (size_t)ti * d;
        float acc = 0.f;
        for (int k = lane; k < d; k += 32) acc = fmaf(pr[k], wr[k], acc);
#pragma unroll
        for (int o = 16; o; o >>= 1) acc += __shfl_xor_sync(0xffffffffu, acc, o);
        if (lane == 0) g_sel_tail[gw] = acc + B[ti];
    }
}

// ---------------- final NLL + mean -------------------------------------------
__global__ void final_kernel(const void* __restrict__ target, float* __restrict__ out)
{
    __shared__ float sh[NROWS];
    int r = threadIdx.x;
    int c = cluster_of(ld_target(target, r));
    float nll;
    if (c == 0)
        nll = g_head_lse[r] - g_sel_head[r];
    else
        nll = (g_head_lse[r] - g_sel_cluster[r]) + (g_tail_lse[r] - g_sel_tail[r]);
    sh[r] = nll;
    __syncthreads();
    for (int off = 512; off; off >>= 1) {
        if (r < off) sh[r] += sh[r + off];
        __syncthreads();
    }
    if (r == 0) out[0] = sh[0] * (1.0f / NROWS);
}

// ============================================================================
// launch
// ============================================================================
extern "C" void kernel_launch(void* const* d_in, const int* in_sizes, int n_in,
                              void* d_out, int out_size)
{
    const float* hidden = (const float*)d_in[0];
    const void*  target = d_in[1];                 // int32 or int64; detected on device
    const float* W0 = (const float*)d_in[2];
    const float* b0 = (const float*)d_in[3];
    const float* proj0 = (const float*)d_in[4];
    const float* W1 = (const float*)d_in[5];
    const float* b1 = (const float*)d_in[6];
    const float* proj1 = (const float*)d_in[7];
    const float* W2 = (const float*)d_in[8];
    const float* b2 = (const float*)d_in[9];
    const float* proj2 = (const float*)d_in[10];
    const float* W3 = (const float*)d_in[11];
    const float* b3 = (const float*)d_in[12];
    const float* proj3 = (const float*)d_in[13];
    const float* cW = (const float*)d_in[14];
    const float* cb = (const float*)d_in[15];
    float* out = (float*)d_out;

    void *vp0, *vp1, *vp2, *vp3, *vpm, *vps, *vhl, *vtl, *vrows, *vcnt;
    cudaGetSymbolAddress(&vp0, g_P0);
    cudaGetSymbolAddress(&vp1, g_P1);
    cudaGetSymbolAddress(&vp2, g_P2);
    cudaGetSymbolAddress(&vp3, g_P3);
    cudaGetSymbolAddress(&vpm, g_pm);
    cudaGetSymbolAddress(&vps, g_ps);
    cudaGetSymbolAddress(&vhl, g_head_lse);
    cudaGetSymbolAddress(&vtl, g_tail_lse);
    cudaGetSymbolAddress(&vrows, g_rows);
    cudaGetSymbolAddress(&vcnt, g_cnt);
    float* P0 = (float*)vp0;  float* P1 = (float*)vp1;
    float* P2 = (float*)vp2;  float* P3 = (float*)vp3;
    float* pm = (float*)vpm;  float* ps = (float*)vps;
    float* head_lse = (float*)vhl;  float* tail_lse = (float*)vtl;
    int* rows = (int*)vrows;  int* cnt = (int*)vcnt;

    detect_kernel<<<1, 256>>>((const int*)target);
    init_kernel<<<1, 32>>>();
    classify_kernel<<<4, 256>>>(target);

    // projections: P_i = hidden[1024,1024] @ proj_i[1024, d_i]
    gemm_kernel<false, false, false><<<dim3(8, 8), 256>>>(hidden, 1024, proj0, nullptr,
        nullptr, nullptr, 1024, 0, P0, 1024, nullptr, nullptr, nullptr, nullptr);
    gemm_kernel<false, false, false><<<dim3(2, 8), 256>>>(hidden, 1024, proj1, nullptr,
        nullptr, nullptr, 256, 0, P1, 256, nullptr, nullptr, nullptr, nullptr);
    gemm_kernel<false, false, false><<<dim3(1, 8), 256>>>(hidden, 1024, proj2, nullptr,
        nullptr, nullptr, 64, 0, P2, 64, nullptr, nullptr, nullptr, nullptr);
    gemm_kernel<false, false, false><<<dim3(1, 8), 256>>>(hidden, 1024, proj3, nullptr,
        nullptr, nullptr, 16, 0, P3, 16, nullptr, nullptr, nullptr, nullptr);

    // head: 20003 logits per row -> streaming LSE partials
    const int nblk_head = (20003 + TN - 1) / TN;   // 157
    gemm_kernel<true, true, true><<<dim3(nblk_head, 8), 256>>>(P0, 1024, W0, cW, b0, cb,
        20003, 20000, nullptr, 0, nullptr, nullptr, pm, ps);
    reduce_lse_kernel<<<NROWS, 128>>>(pm, ps, nblk_head, head_lse, nullptr, nullptr);

    // individual logits (target col / cluster cols / tail target col)
    sel_kernel<<<128, 256>>>(target, W0, b0, W1, b1, W2, b2, W3, b3, cW, cb);

    // tail cluster 1: V=20000, d=256
    {
        const int nblk = (20000 + TN - 1) / TN;    // 157
        gemm_kernel<true, true, false><<<dim3(nblk, 8), 256>>>(P1, 256, W1, nullptr, b1,
            nullptr, 20000, 0, nullptr, 0, rows + 0 * NROWS, cnt + 0, pm, ps);
        reduce_lse_kernel<<<NROWS, 128>>>(pm, ps, nblk, tail_lse, rows + 0 * NROWS, cnt + 0);
    }
    // tail cluster 2: V=160000, d=64
    {
        const int nblk = (160000 + TN - 1) / TN;   // 1250
        gemm_kernel<true, true, false><<<dim3(nblk, 8), 256>>>(P2, 64, W2, nullptr, b2,
            nullptr, 160000, 0, nullptr, 0, rows + 1 * NROWS, cnt + 1, pm, ps);
        reduce_lse_kernel<<<NROWS, 128>>>(pm, ps, nblk, tail_lse, rows + 1 * NROWS, cnt + 1);
    }
    // tail cluster 3: V=67735, d=16
    {
        const int nblk = (67735 + TN - 1) / TN;    // 530
        gemm_kernel<true, true, false><<<dim3(nblk, 8), 256>>>(P3, 16, W3, nullptr, b3,
            nullptr, 67735, 0, nullptr, 0, rows + 2 * NROWS, cnt + 2, pm, ps);
        reduce_lse_kernel<<<NROWS, 128>>>(pm, ps, nblk, tail_lse, rows + 2 * NROWS, cnt + 2);
    }

    final_kernel<<<1, NROWS>>>(target, out);
    (void)in_sizes; (void)n_in; (void)out_size;
}

// round 14
// speedup vs baseline: 1.0069x; 1.0063x over previous
#include <cuda_runtime.h>
#include <math.h>
#include <stdint.h>

// ============================================================================
// ProjectedAdaptiveLogSoftmax — fused adaptive softmax NLL (mean) on GB300
//
// Stages (all on one stream, graph-capturable, no allocations):
//   0. detect    : probe target dtype (int32 vs int64) -> g_is64 flag
//   1. init      : zero per-cluster row counters
//   2. classify  : compact row indices per tail cluster (atomics; result set
//                  is deterministic, per-row outputs are order-independent)
//   3. proj GEMM : P_i = hidden @ proj_i   (stored in __device__ scratch)
//   4. head GEMM : streaming (m, s) logsumexp partials over 20003 logits
//   5. reduce    : head LSE per row
//   6. sel       : the few individual logits needed (target col, cluster cols,
//                  tail target col) via one warp-dot per row
//   7. tail GEMMs: streaming LSE partials, gathered over compacted row lists
//   8. final     : per-row NLL, tree-reduced mean -> d_out[0]
// ============================================================================

#define NROWS   1024
#define DHID    1024
#define TM      128
#define TN      128
#define TK      8
#define PSTRIDE 1280   // >= ceil(160000/128) = 1250 partial blocks per row

#define CUT1 20000
#define CUT2 40000
#define CUT3 200000

// ------------------------- device scratch (static) -------------------------
static __device__ float g_P0[NROWS * 1024];
static __device__ float g_P1[NROWS * 256];
static __device__ float g_P2[NROWS * 64];
static __device__ float g_P3[NROWS * 16];
static __device__ float g_pm[NROWS * PSTRIDE];
static __device__ float g_ps[NROWS * PSTRIDE];
static __device__ float g_head_lse[NROWS];
static __device__ float g_tail_lse[NROWS];
static __device__ float g_sel_head[NROWS];
static __device__ float g_sel_cluster[NROWS];
static __device__ float g_sel_tail[NROWS];
static __device__ int   g_rows[3 * NROWS];
static __device__ int   g_cnt[3];
static __device__ int   g_is64;

// ------------------------------ helpers ------------------------------------
__device__ __forceinline__ int cluster_of(long long t) {
    return (t < CUT1) ? 0 : (t < CUT2) ? 1 : (t < CUT3) ? 2 : 3;
}

// dtype-agnostic target load (dispatches on runtime-detected width)
__device__ __forceinline__ long long ld_target(const void* p, int r) {
    if (g_is64) return ((const long long*)p)[r];
    return (long long)((const int*)p)[r];
}

// online logsumexp merge of (m1,s1) <- (m1,s1) + (m2,s2)
__device__ __forceinline__ void lse_combine(float& m, float& s, float m2, float s2) {
    float mn = fmaxf(m, m2);
    if (mn == -INFINITY) { m = mn; s = 0.f; return; }   // both empty
    s = s * __expf(m - mn) + s2 * __expf(m2 - mn);      // expf(-inf)=0, expf(0)=1
    m = mn;
}

// ---- dtype probe: view first 1024 int32 words (valid for either dtype).
// int64 targets (< 2^18) -> all 512 odd words are hi==0.
// int32 targets -> odd words are random values, ~surely nonzero somewhere.
__global__ void detect_kernel(const int* __restrict__ t32) {
    __shared__ int nz;
    if (threadIdx.x == 0) nz = 0;
    __syncthreads();
    for (int i = 2 * threadIdx.x + 1; i < NROWS; i += 2 * blockDim.x)
        if (t32[i] != 0) nz = 1;
    __syncthreads();
    if (threadIdx.x == 0) g_is64 = (nz == 0);
}

__global__ void init_kernel() {
    if (threadIdx.x < 3) g_cnt[threadIdx.x] = 0;
}

__global__ void classify_kernel(const void* __restrict__ target) {
    int r = blockIdx.x * blockDim.x + threadIdx.x;
    if (r >= NROWS) return;
    int c = cluster_of(ld_target(target, r));
    if (c > 0) {
        int p = atomicAdd(&g_cnt[c - 1], 1);
        g_rows[(c - 1) * NROWS + p] = r;
    }
}

// ============================================================================
// Tiled GEMM, fp32 with packed fma.rn.f32x2 (FFMA2) accumulation.
//   BNT  : B is [V, dK] row-major (weights; we need B^T)  vs [dK, V] (proj)
//   LSE  : emit per-(row, col-block) logsumexp partials    vs store C
//   HEAD : B is concat(W0[V0,dK], cluster_W[V-V0,dK]) with bias2 for tail cols
// Tile: 128x128 output, K-step 8, 256 threads, 8x8 micro-tile per thread.
// ============================================================================
template <bool BNT, bool LSE, bool HEAD>
__global__ __launch_bounds__(256, 2)
void gemm_kernel(const float* __restrict__ A, int dK,
                 const float* __restrict__ B, const float* __restrict__ B2,
                 const float* __restrict__ bias, const float* __restrict__ bias2,
                 int V, int V0,
                 float* __restrict__ C, int ldc,
                 const int* __restrict__ rowlist, const int* __restrict__ cntptr,
                 float* __restrict__ pm, float* __restrict__ ps)
{
    const int cnt  = cntptr ? *cntptr : NROWS;
    const int row0 = blockIdx.y * TM;
    if (rowlist && row0 >= cnt) return;           // dead row tile (tail clusters)
    const int col0 = blockIdx.x * TN;

    __shared__ int   rid[TM];
    __shared__ float As[TK][TM];
    __shared__ float Bs[TK][TN];

    const int tid = threadIdx.x;
    const int tx  = tid & 15;
    const int ty  = tid >> 4;

    if (tid < TM) {
        int pos  = row0 + tid;
        rid[tid] = rowlist ? (pos < cnt ? rowlist[pos] : 0) : pos;
    }

    // packed f32x2 accumulators: acc[i][j] holds cols (2j, 2j+1) of row i
    unsigned long long acc[8][4];
#pragma unroll
    for (int i = 0; i < 8; i++)
#pragma unroll
        for (int j = 0; j < 4; j++) acc[i][j] = 0ull;

    // per-thread load coords
    const int am = tid >> 1;            // 0..127 (row within tile)
    const int ak = (tid & 1) * 4;       // 0 or 4 (k within TK)
    const int pk = tid >> 5;            // proj-mode: k within TK (0..7)
    const int pn = (tid & 31) * 4;      // proj-mode: col within tile

    for (int k0 = 0; k0 < dK; k0 += TK) {
        __syncthreads();   // protect smem from previous iteration's readers (and rid)

        // ---- load A tile: As[k][m] = A[rid[m]][k0+k]
        {
            const float4 v = *(const float4*)(A + (size_t)rid[am] * dK + k0 + ak);
            As[ak + 0][am] = v.x; As[ak + 1][am] = v.y;
            As[ak + 2][am] = v.z; As[ak + 3][am] = v.w;
        }
        // ---- load B tile
        if (BNT) {          // Bs[k][n] = W[col0+n][k0+k]
            int cg = col0 + am;
            float4 v = make_float4(0.f, 0.f, 0.f, 0.f);
            if (HEAD) {
                if (cg < V0)      v = *(const float4*)(B  + (size_t)cg * dK + k0 + ak);
                else if (cg < V)  v = *(const float4*)(B2 + (size_t)(cg - V0) * dK + k0 + ak);
            } else {
                if (cg < V)       v = *(const float4*)(B  + (size_t)cg * dK + k0 + ak);
            }
            Bs[ak + 0][am] = v.x; Bs[ak + 1][am] = v.y;
            Bs[ak + 2][am] = v.z; Bs[ak + 3][am] = v.w;
        } else {            // Bs[k][n] = proj[k0+k][col0+n]  (contiguous in n)
            int cg = col0 + pn;
            float4 v = make_float4(0.f, 0.f, 0.f, 0.f);
            if (cg < V)  // V is a multiple of 4 for all projections
                v = *(const float4*)(B + (size_t)(k0 + pk) * V + cg);
            *(float4*)&Bs[pk][pn] = v;
        }
        __syncthreads();

        // ---- compute: 8x8 micro-tile, 32 FFMA2 per k
#pragma unroll
        for (int k = 0; k < TK; k++) {
            float a[8], b[8];
            *(float4*)(a)     = *(const float4*)&As[k][ty * 8];
            *(float4*)(a + 4) = *(const float4*)&As[k][ty * 8 + 4];
            *(float4*)(b)     = *(const float4*)&Bs[k][tx * 8];
            *(float4*)(b + 4) = *(const float4*)&Bs[k][tx * 8 + 4];

            unsigned long long av[8], bv[4];
#pragma unroll
            for (int i = 0; i < 8; i++)
                asm("mov.b64 %0, {%1, %1};" : "=l"(av[i]) : "f"(a[i]));
#pragma unroll
            for (int j = 0; j < 4; j++)
                asm("mov.b64 %0, {%1, %2};" : "=l"(bv[j]) : "f"(b[2 * j]), "f"(b[2 * j + 1]));
#pragma unroll
            for (int i = 0; i < 8; i++)
#pragma unroll
                for (int j = 0; j < 4; j++)
                    asm("fma.rn.f32x2 %0, %1, %2, %0;"
                        : "+l"(acc[i][j]) : "l"(av[i]), "l"(bv[j]));
        }
    }

    // unpack accumulators
    float accf[8][8];
#pragma unroll
    for (int i = 0; i < 8; i++)
#pragma unroll
        for (int j = 0; j < 4; j++)
            asm("mov.b64 {%0, %1}, %2;"
                : "=f"(accf[i][2 * j]), "=f"(accf[i][2 * j + 1]) : "l"(acc[i][j]));

    if (!LSE) {
        // store C (projection results); rows are identity here
#pragma unroll
        for (int i = 0; i < 8; i++) {
            int r = rid[ty * 8 + i];
#pragma unroll
            for (int j = 0; j < 8; j++) {
                int cg = col0 + tx * 8 + j;
                if (cg < V) C[(size_t)r * ldc + cg] = accf[i][j];
            }
        }
    } else {
        // add bias, mask OOB cols to -inf, per-row (m,s) over the 128-col tile
        const int cbase = col0 + tx * 8;
        float bj[8];
#pragma unroll
        for (int j = 0; j < 8; j++) {
            int cg = cbase + j;
            float bb = 0.f;
            if (cg < V) bb = (HEAD && cg >= V0) ? bias2[cg - V0] : bias[cg];
            bj[j] = bb;
        }
#pragma unroll
        for (int i = 0; i < 8; i++) {
            float m = -INFINITY;
            float v[8];
#pragma unroll
            for (int j = 0; j < 8; j++) {
                int cg = cbase + j;
                v[j] = (cg < V) ? (accf[i][j] + bj[j]) : -INFINITY;
                m = fmaxf(m, v[j]);
            }
            float s = 0.f;
            if (m > -INFINITY) {
#pragma unroll
                for (int j = 0; j < 8; j++) s += __expf(v[j] - m);
            }
            // reduce across the 16 lanes owning this row (xor<16 stays in group)
#pragma unroll
            for (int off = 8; off; off >>= 1) {
                float mo = __shfl_xor_sync(0xffffffffu, m, off);
                float so = __shfl_xor_sync(0xffffffffu, s, off);
                lse_combine(m, s, mo, so);
            }
            if (tx == 0) {
                int pidx = row0 + ty * 8 + i;   // list position (== row when identity)
                pm[(size_t)pidx * PSTRIDE + blockIdx.x] = m;
                ps[(size_t)pidx * PSTRIDE + blockIdx.x] = s;
            }
        }
    }
}

// ---------------- merge LSE partials per row --------------------------------
__global__ void reduce_lse_kernel(const float* __restrict__ pm, const float* __restrict__ ps,
                                  int nblk, float* __restrict__ out,
                                  const int* __restrict__ rowlist, const int* __restrict__ cntptr)
{
    int idx = blockIdx.x;
    if (cntptr && idx >= *cntptr) return;
    int tid = threadIdx.x;
    float m = -INFINITY, s = 0.f;
    for (int b = tid; b < nblk; b += 128)
        lse_combine(m, s, pm[(size_t)idx * PSTRIDE + b], ps[(size_t)idx * PSTRIDE + b]);
    __shared__ float sm[128], ss[128];
    sm[tid] = m; ss[tid] = s;
    __syncthreads();
    for (int off = 64; off; off >>= 1) {
        if (tid < off) {
            float mm = sm[tid], sv = ss[tid];
            lse_combine(mm, sv, sm[tid + off], ss[tid + off]);
            sm[tid] = mm; ss[tid] = sv;
        }
        __syncthreads();
    }
    if (tid == 0) {
        int row = rowlist ? rowlist[idx] : idx;
        out[row] = sm[0] + logf(ss[0]);
    }
}

// ---------------- selected logits: one warp per row --------------------------
__global__ void sel_kernel(const void* __restrict__ target,
                           const float* __restrict__ W0, const float* __restrict__ b0,
                           const float* __restrict__ W1, const float* __restrict__ b1,
                           const float* __restrict__ W2, const float* __restrict__ b2,
                           const float* __restrict__ W3, const float* __restrict__ b3,
                           const float* __restrict__ cW, const float* __restrict__ cb)
{
    int gw   = (blockIdx.x * blockDim.x + threadIdx.x) >> 5;
    int lane = threadIdx.x & 31;
    if (gw >= NROWS) return;
    long long t = ld_target(target, gw);
    int c = cluster_of(t);
    const float* p0 = g_P0 + (size_t)gw * 1024;

    // head token logit (t0 = clip(target, 0, 19999))
    {
        int colh = (int)(t < CUT1 ? t : (long long)(CUT1 - 1));
        const float* w = W0 + (size_t)colh * 1024;
        float acc = 0.f;
        for (int k = lane; k < 1024; k += 32) acc = fmaf(p0[k], w[k], acc);
#pragma unroll
        for (int o = 16; o; o >>= 1) acc += __shfl_xor_sync(0xffffffffu, acc, o);
        if (lane == 0) g_sel_head[gw] = acc + b0[colh];
    }
    if (c > 0) {
        // head cluster column: head_lp[:, -c] -> concat col (20003 - c) -> cluster_W[3-c]
        {
            const float* w = cW + (size_t)(3 - c) * 1024;
            float acc = 0.f;
            for (int k = lane; k < 1024; k += 32) acc = fmaf(p0[k], w[k], acc);
#pragma unroll
            for (int o = 16; o; o >>= 1) acc += __shfl_xor_sync(0xffffffffu, acc, o);
            if (lane == 0) g_sel_cluster[gw] = acc + cb[3 - c];
        }
        // tail token logit
        int lo = (c == 1) ? CUT1 : (c == 2) ? CUT2 : CUT3;
        int d  = (c == 1) ? 256  : (c == 2) ? 64   : 16;
        const float* P = (c == 1) ? g_P1 : (c == 2) ? g_P2 : g_P3;
        const float* W = (c == 1) ? W1 : (c == 2) ? W2 : W3;
        const float* B = (c == 1) ? b1 : (c == 2) ? b2 : b3;
        int ti = (int)(t - lo);
        const float* pr = P + (size_t)gw * d;
        const float* wr = W + (size_t)ti * d;
        float acc = 0.f;
        for (int k = lane; k < d; k += 32) acc = fmaf(pr[k], wr[k], acc);
#pragma unroll
        for (int o = 16; o; o >>= 1) acc += __shfl_xor_sync(0xffffffffu, acc, o);
        if (lane == 0) g_sel_tail[gw] = acc + B[ti];
    }
}

// ---------------- final NLL + mean -------------------------------------------
__global__ void final_kernel(const void* __restrict__ target, float* __restrict__ out)
{
    __shared__ float sh[NROWS];
    int r = threadIdx.x;
    int c = cluster_of(ld_target(target, r));
    float nll;
    if (c == 0)
        nll = g_head_lse[r] - g_sel_head[r];
    else
        nll = (g_head_lse[r] - g_sel_cluster[r]) + (g_tail_lse[r] - g_sel_tail[r]);
    sh[r] = nll;
    __syncthreads();
    for (int off = 512; off; off >>= 1) {
        if (r < off) sh[r] += sh[r + off];
        __syncthreads();
    }
    if (r == 0) out[0] = sh[0] * (1.0f / NROWS);
}

// ============================================================================
// launch
// ============================================================================
extern "C" void kernel_launch(void* const* d_in, const int* in_sizes, int n_in,
                              void* d_out, int out_size)
{
    const float* hidden = (const float*)d_in[0];
    const void*  target = d_in[1];                 // int32 or int64; detected on device
    const float* W0 = (const float*)d_in[2];
    const float* b0 = (const float*)d_in[3];
    const float* proj0 = (const float*)d_in[4];
    const float* W1 = (const float*)d_in[5];
    const float* b1 = (const float*)d_in[6];
    const float* proj1 = (const float*)d_in[7];
    const float* W2 = (const float*)d_in[8];
    const float* b2 = (const float*)d_in[9];
    const float* proj2 = (const float*)d_in[10];
    const float* W3 = (const float*)d_in[11];
    const float* b3 = (const float*)d_in[12];
    const float* proj3 = (const float*)d_in[13];
    const float* cW = (const float*)d_in[14];
    const float* cb = (const float*)d_in[15];
    float* out = (float*)d_out;

    void *vp0, *vp1, *vp2, *vp3, *vpm, *vps, *vhl, *vtl, *vrows, *vcnt;
    cudaGetSymbolAddress(&vp0, g_P0);
    cudaGetSymbolAddress(&vp1, g_P1);
    cudaGetSymbolAddress(&vp2, g_P2);
    cudaGetSymbolAddress(&vp3, g_P3);
    cudaGetSymbolAddress(&vpm, g_pm);
    cudaGetSymbolAddress(&vps, g_ps);
    cudaGetSymbolAddress(&vhl, g_head_lse);
    cudaGetSymbolAddress(&vtl, g_tail_lse);
    cudaGetSymbolAddress(&vrows, g_rows);
    cudaGetSymbolAddress(&vcnt, g_cnt);
    float* P0 = (float*)vp0;  float* P1 = (float*)vp1;
    float* P2 = (float*)vp2;  float* P3 = (float*)vp3;
    float* pm = (float*)vpm;  float* ps = (float*)vps;
    float* head_lse = (float*)vhl;  float* tail_lse = (float*)vtl;
    int* rows = (int*)vrows;  int* cnt = (int*)vcnt;

    detect_kernel<<<1, 256>>>((const int*)target);
    init_kernel<<<1, 32>>>();
    classify_kernel<<<4, 256>>>(target);

    // projections: P_i = hidden[1024,1024] @ proj_i[1024, d_i]
    gemm_kernel<false, false, false><<<dim3(8, 8), 256>>>(hidden, 1024, proj0, nullptr,
        nullptr, nullptr, 1024, 0, P0, 1024, nullptr, nullptr, nullptr, nullptr);
    gemm_kernel<false, false, false><<<dim3(2, 8), 256>>>(hidden, 1024, proj1, nullptr,
        nullptr, nullptr, 256, 0, P1, 256, nullptr, nullptr, nullptr, nullptr);
    gemm_kernel<false, false, false><<<dim3(1, 8), 256>>>(hidden, 1024, proj2, nullptr,
        nullptr, nullptr, 64, 0, P2, 64, nullptr, nullptr, nullptr, nullptr);
    gemm_kernel<false, false, false><<<dim3(1, 8), 256>>>(hidden, 1024, proj3, nullptr,
        nullptr, nullptr, 16, 0, P3, 16, nullptr, nullptr, nullptr, nullptr);

    // head: 20003 logits per row -> streaming LSE partials
    const int nblk_head = (20003 + TN - 1) / TN;   // 157
    gemm_kernel<true, true, true><<<dim3(nblk_head, 8), 256>>>(P0, 1024, W0, cW, b0, cb,
        20003, 20000, nullptr, 0, nullptr, nullptr, pm, ps);
    reduce_lse_kernel<<<NROWS, 128>>>(pm, ps, nblk_head, head_lse, nullptr, nullptr);

    // individual logits (target col / cluster cols / tail target col)
    sel_kernel<<<128, 256>>>(target, W0, b0, W1, b1, W2, b2, W3, b3, cW, cb);

    // tail cluster 1: V=20000, d=256
    {
        const int nblk = (20000 + TN - 1) / TN;    // 157
        gemm_kernel<true, true, false><<<dim3(nblk, 8), 256>>>(P1, 256, W1, nullptr, b1,
            nullptr, 20000, 0, nullptr, 0, rows + 0 * NROWS, cnt + 0, pm, ps);
        reduce_lse_kernel<<<NROWS, 128>>>(pm, ps, nblk, tail_lse, rows + 0 * NROWS, cnt + 0);
    }
    // tail cluster 2: V=160000, d=64
    {
        const int nblk = (160000 + TN - 1) / TN;   // 1250
        gemm_kernel<true, true, false><<<dim3(nblk, 8), 256>>>(P2, 64, W2, nullptr, b2,
            nullptr, 160000, 0, nullptr, 0, rows + 1 * NROWS, cnt + 1, pm, ps);
        reduce_lse_kernel<<<NROWS, 128>>>(pm, ps, nblk, tail_lse, rows + 1 * NROWS, cnt + 1);
    }
    // tail cluster 3: V=67735, d=16
    {
        const int nblk = (67735 + TN - 1) / TN;    // 530
        gemm_kernel<true, true, false><<<dim3(nblk, 8), 256>>>(P3, 16, W3, nullptr, b3,
            nullptr, 67735, 0, nullptr, 0, rows + 2 * NROWS, cnt + 2, pm, ps);
        reduce_lse_kernel<<<NROWS, 128>>>(pm, ps, nblk, tail_lse, rows + 2 * NROWS, cnt + 2);
    }

    final_kernel<<<1, NROWS>>>(target, out);
    (void)in_sizes; (void)n_in; (void)out_size;
}

// round 15
// speedup vs baseline: 1.0074x; 1.0005x over previous
#include <cuda_runtime.h>
#include <math.h>
#include <stdint.h>

// ============================================================================
// ProjectedAdaptiveLogSoftmax — fused adaptive softmax NLL (mean) on GB300
//
// Stages (all on one stream, graph-capturable, no allocations):
//   0. detect    : probe target dtype (int32 vs int64) -> g_is64 flag
//   1. init      : zero per-cluster row counters
//   2. classify  : compact row indices per tail cluster (atomics; result set
//                  is deterministic, per-row outputs are order-independent)
//   3. proj GEMM : P_i = hidden @ proj_i   (stored in __device__ scratch)
//   4. head GEMM : streaming (m, s) logsumexp partials over 20003 logits
//   5. reduce    : head LSE per row
//   6. sel       : the few individual logits needed (target col, cluster cols,
//                  tail target col) via one warp-dot per row
//   7. tail GEMMs: streaming LSE partials, gathered over compacted row lists
//   8. final     : per-row NLL, tree-reduced mean -> d_out[0]
// ============================================================================

#define NROWS   1024
#define DHID    1024
#define TM      128
#define TN      128
#define TK      8
#define PSTRIDE 1280   // >= ceil(160000/128) = 1250 partial blocks per row

#define CUT1 20000
#define CUT2 40000
#define CUT3 200000

// ------------------------- device scratch (static) -------------------------
static __device__ float g_P0[NROWS * 1024];
static __device__ float g_P1[NROWS * 256];
static __device__ float g_P2[NROWS * 64];
static __device__ float g_P3[NROWS * 16];
static __device__ float g_pm[NROWS * PSTRIDE];
static __device__ float g_ps[NROWS * PSTRIDE];
static __device__ float g_head_lse[NROWS];
static __device__ float g_tail_lse[NROWS];
static __device__ float g_sel_head[NROWS];
static __device__ float g_sel_cluster[NROWS];
static __device__ float g_sel_tail[NROWS];
static __device__ int   g_rows[3 * NROWS];
static __device__ int   g_cnt[3];
static __device__ int   g_is64;

// ------------------------------ helpers ------------------------------------
__device__ __forceinline__ int cluster_of(long long t) {
    return (t < CUT1) ? 0 : (t < CUT2) ? 1 : (t < CUT3) ? 2 : 3;
}

// dtype-agnostic target load (dispatches on runtime-detected width)
__device__ __forceinline__ long long ld_target(const void* p, int r) {
    if (g_is64) return ((const long long*)p)[r];
    return (long long)((const int*)p)[r];
}

// online logsumexp merge of (m1,s1) <- (m1,s1) + (m2,s2)
__device__ __forceinline__ void lse_combine(float& m, float& s, float m2, float s2) {
    float mn = fmaxf(m, m2);
    if (mn == -INFINITY) { m = mn; s = 0.f; return; }   // both empty
    s = s * __expf(m - mn) + s2 * __expf(m2 - mn);      // expf(-inf)=0, expf(0)=1
    m = mn;
}

// ---- dtype probe: view first 1024 int32 words (valid for either dtype).
// int64 targets (< 2^18) -> all 512 odd words are hi==0.
// int32 targets -> odd words are random values, ~surely nonzero somewhere.
__global__ void detect_kernel(const int* __restrict__ t32) {
    __shared__ int nz;
    if (threadIdx.x == 0) nz = 0;
    __syncthreads();
    for (int i = 2 * threadIdx.x + 1; i < NROWS; i += 2 * blockDim.x)
        if (t32[i] != 0) nz = 1;
    __syncthreads();
    if (threadIdx.x == 0) g_is64 = (nz == 0);
}

__global__ void init_kernel() {
    if (threadIdx.x < 3) g_cnt[threadIdx.x] = 0;
}

__global__ void classify_kernel(const void* __restrict__ target) {
    int r = blockIdx.x * blockDim.x + threadIdx.x;
    if (r >= NROWS) return;
    int c = cluster_of(ld_target(target, r));
    if (c > 0) {
        int p = atomicAdd(&g_cnt[c - 1], 1);
        g_rows[(c - 1) * NROWS + p] = r;
    }
}

// ============================================================================
// Tiled GEMM, fp32 with packed fma.rn.f32x2 (FFMA2) accumulation.
//   BNT  : B is [V, dK] row-major (weights; we need B^T)  vs [dK, V] (proj)
//   LSE  : emit per-(row, col-block) logsumexp partials    vs store C
//   HEAD : B is concat(W0[V0,dK], cluster_W[V-V0,dK]) with bias2 for tail cols
// Tile: 128x128 output, K-step 8, 256 threads, 8x8 micro-tile per thread.
// ============================================================================
template <bool BNT, bool LSE, bool HEAD>
__global__ __launch_bounds__(256, 2)
void gemm_kernel(const float* __restrict__ A, int dK,
                 const float* __restrict__ B, const float* __restrict__ B2,
                 const float* __restrict__ bias, const float* __restrict__ bias2,
                 int V, int V0,
                 float* __restrict__ C, int ldc,
                 const int* __restrict__ rowlist, const int* __restrict__ cntptr,
                 float* __restrict__ pm, float* __restrict__ ps)
{
    const int cnt  = cntptr ? *cntptr : NROWS;
    const int row0 = blockIdx.y * TM;
    if (rowlist && row0 >= cnt) return;           // dead row tile (tail clusters)
    const int col0 = blockIdx.x * TN;

    __shared__ int   rid[TM];
    __shared__ float As[TK][TM];
    __shared__ float Bs[TK][TN];

    const int tid = threadIdx.x;
    const int tx  = tid & 15;
    const int ty  = tid >> 4;

    if (tid < TM) {
        int pos  = row0 + tid;
        rid[tid] = rowlist ? (pos < cnt ? rowlist[pos] : 0) : pos;
    }

    // packed f32x2 accumulators: acc[i][j] holds cols (2j, 2j+1) of row i
    unsigned long long acc[8][4];
#pragma unroll
    for (int i = 0; i < 8; i++)
#pragma unroll
        for (int j = 0; j < 4; j++) acc[i][j] = 0ull;

    // per-thread load coords
    const int am = tid >> 1;            // 0..127 (row within tile)
    const int ak = (tid & 1) * 4;       // 0 or 4 (k within TK)
    const int pk = tid >> 5;            // proj-mode: k within TK (0..7)
    const int pn = (tid & 31) * 4;      // proj-mode: col within tile

    for (int k0 = 0; k0 < dK; k0 += TK) {
        __syncthreads();   // protect smem from previous iteration's readers (and rid)

        // ---- load A tile: As[k][m] = A[rid[m]][k0+k]
        {
            const float4 v = *(const float4*)(A + (size_t)rid[am] * dK + k0 + ak);
            As[ak + 0][am] = v.x; As[ak + 1][am] = v.y;
            As[ak + 2][am] = v.z; As[ak + 3][am] = v.w;
        }
        // ---- load B tile
        if (BNT) {          // Bs[k][n] = W[col0+n][k0+k]
            int cg = col0 + am;
            float4 v = make_float4(0.f, 0.f, 0.f, 0.f);
            if (HEAD) {
                if (cg < V0)      v = *(const float4*)(B  + (size_t)cg * dK + k0 + ak);
                else if (cg < V)  v = *(const float4*)(B2 + (size_t)(cg - V0) * dK + k0 + ak);
            } else {
                if (cg < V)       v = *(const float4*)(B  + (size_t)cg * dK + k0 + ak);
            }
            Bs[ak + 0][am] = v.x; Bs[ak + 1][am] = v.y;
            Bs[ak + 2][am] = v.z; Bs[ak + 3][am] = v.w;
        } else {            // Bs[k][n] = proj[k0+k][col0+n]  (contiguous in n)
            int cg = col0 + pn;
            float4 v = make_float4(0.f, 0.f, 0.f, 0.f);
            if (cg < V)  // V is a multiple of 4 for all projections
                v = *(const float4*)(B + (size_t)(k0 + pk) * V + cg);
            *(float4*)&Bs[pk][pn] = v;
        }
        __syncthreads();

        // ---- compute: 8x8 micro-tile, 32 FFMA2 per k
#pragma unroll
        for (int k = 0; k < TK; k++) {
            float a[8], b[8];
            *(float4*)(a)     = *(const float4*)&As[k][ty * 8];
            *(float4*)(a + 4) = *(const float4*)&As[k][ty * 8 + 4];
            *(float4*)(b)     = *(const float4*)&Bs[k][tx * 8];
            *(float4*)(b + 4) = *(const float4*)&Bs[k][tx * 8 + 4];

            unsigned long long av[8], bv[4];
#pragma unroll
            for (int i = 0; i < 8; i++)
                asm("mov.b64 %0, {%1, %1};" : "=l"(av[i]) : "f"(a[i]));
#pragma unroll
            for (int j = 0; j < 4; j++)
                asm("mov.b64 %0, {%1, %2};" : "=l"(bv[j]) : "f"(b[2 * j]), "f"(b[2 * j + 1]));
#pragma unroll
            for (int i = 0; i < 8; i++)
#pragma unroll
                for (int j = 0; j < 4; j++)
                    asm("fma.rn.f32x2 %0, %1, %2, %0;"
                        : "+l"(acc[i][j]) : "l"(av[i]), "l"(bv[j]));
        }
    }

    // unpack accumulators
    float accf[8][8];
#pragma unroll
    for (int i = 0; i < 8; i++)
#pragma unroll
        for (int j = 0; j < 4; j++)
            asm("mov.b64 {%0, %1}, %2;"
                : "=f"(accf[i][2 * j]), "=f"(accf[i][2 * j + 1]) : "l"(acc[i][j]));

    if (!LSE) {
        // store C (projection results); rows are identity here
#pragma unroll
        for (int i = 0; i < 8; i++) {
            int r = rid[ty * 8 + i];
#pragma unroll
            for (int j = 0; j < 8; j++) {
                int cg = col0 + tx * 8 + j;
                if (cg < V) C[(size_t)r * ldc + cg] = accf[i][j];
            }
        }
    } else {
        // add bias, mask OOB cols to -inf, per-row (m,s) over the 128-col tile
        const int cbase = col0 + tx * 8;
        float bj[8];
#pragma unroll
        for (int j = 0; j < 8; j++) {
            int cg = cbase + j;
            float bb = 0.f;
            if (cg < V) bb = (HEAD && cg >= V0) ? bias2[cg - V0] : bias[cg];
            bj[j] = bb;
        }
#pragma unroll
        for (int i = 0; i < 8; i++) {
            float m = -INFINITY;
            float v[8];
#pragma unroll
            for (int j = 0; j < 8; j++) {
                int cg = cbase + j;
                v[j] = (cg < V) ? (accf[i][j] + bj[j]) : -INFINITY;
                m = fmaxf(m, v[j]);
            }
            float s = 0.f;
            if (m > -INFINITY) {
#pragma unroll
                for (int j = 0; j < 8; j++) s += __expf(v[j] - m);
            }
            // reduce across the 16 lanes owning this row (xor<16 stays in group)
#pragma unroll
            for (int off = 8; off; off >>= 1) {
                float mo = __shfl_xor_sync(0xffffffffu, m, off);
                float so = __shfl_xor_sync(0xffffffffu, s, off);
                lse_combine(m, s, mo, so);
            }
            if (tx == 0) {
                int pidx = row0 + ty * 8 + i;   // list position (== row when identity)
                pm[(size_t)pidx * PSTRIDE + blockIdx.x] = m;
                ps[(size_t)pidx * PSTRIDE + blockIdx.x] = s;
            }
        }
    }
}

// ---------------- merge LSE partials per row --------------------------------
__global__ void reduce_lse_kernel(const float* __restrict__ pm, const float* __restrict__ ps,
                                  int nblk, float* __restrict__ out,
                                  const int* __restrict__ rowlist, const int* __restrict__ cntptr)
{
    int idx = blockIdx.x;
    if (cntptr && idx >= *cntptr) return;
    int tid = threadIdx.x;
    float m = -INFINITY, s = 0.f;
    for (int b = tid; b < nblk; b += 128)
        lse_combine(m, s, pm[(size_t)idx * PSTRIDE + b], ps[(size_t)idx * PSTRIDE + b]);
    __shared__ float sm[128], ss[128];
    sm[tid] = m; ss[tid] = s;
    __syncthreads();
    for (int off = 64; off; off >>= 1) {
        if (tid < off) {
            float mm = sm[tid], sv = ss[tid];
            lse_combine(mm, sv, sm[tid + off], ss[tid + off]);
            sm[tid] = mm; ss[tid] = sv;
        }
        __syncthreads();
    }
    if (tid == 0) {
        int row = rowlist ? rowlist[idx] : idx;
        out[row] = sm[0] + logf(ss[0]);
    }
}

// ---------------- selected logits: one warp per row --------------------------
__global__ void sel_kernel(const void* __restrict__ target,
                           const float* __restrict__ W0, const float* __restrict__ b0,
                           const float* __restrict__ W1, const float* __restrict__ b1,
                           const float* __restrict__ W2, const float* __restrict__ b2,
                           const float* __restrict__ W3, const float* __restrict__ b3,
                           const float* __restrict__ cW, const float* __restrict__ cb)
{
    int gw   = (blockIdx.x * blockDim.x + threadIdx.x) >> 5;
    int lane = threadIdx.x & 31;
    if (gw >= NROWS) return;
    long long t = ld_target(target, gw);
    int c = cluster_of(t);
    const float* p0 = g_P0 + (size_t)gw * 1024;

    // head token logit (t0 = clip(target, 0, 19999))
    {
        int colh = (int)(t < CUT1 ? t : (long long)(CUT1 - 1));
        const float* w = W0 + (size_t)colh * 1024;
        float acc = 0.f;
        for (int k = lane; k < 1024; k += 32) acc = fmaf(p0[k], w[k], acc);
#pragma unroll
        for (int o = 16; o; o >>= 1) acc += __shfl_xor_sync(0xffffffffu, acc, o);
        if (lane == 0) g_sel_head[gw] = acc + b0[colh];
    }
    if (c > 0) {
        // head cluster column: head_lp[:, -c] -> concat col (20003 - c) -> cluster_W[3-c]
        {
            const float* w = cW + (size_t)(3 - c) * 1024;
            float acc = 0.f;
            for (int k = lane; k < 1024; k += 32) acc = fmaf(p0[k], w[k], acc);
#pragma unroll
            for (int o = 16; o; o >>= 1) acc += __shfl_xor_sync(0xffffffffu, acc, o);
            if (lane == 0) g_sel_cluster[gw] = acc + cb[3 - c];
        }
        // tail token logit
        int lo = (c == 1) ? CUT1 : (c == 2) ? CUT2 : CUT3;
        int d  = (c == 1) ? 256  : (c == 2) ? 64   : 16;
        const float* P = (c == 1) ? g_P1 : (c == 2) ? g_P2 : g_P3;
        const float* W = (c == 1) ? W1 : (c == 2) ? W2 : W3;
        const float* B = (c == 1) ? b1 : (c == 2) ? b2 : b3;
        int ti = (int)(t - lo);
        const float* pr = P + (size_t)gw * d;
        const float* wr = W + (size_t)ti * d;
        float acc = 0.f;
        for (int k = lane; k < d; k += 32) acc = fmaf(pr[k], wr[k], acc);
#pragma unroll
        for (int o = 16; o; o >>= 1) acc += __shfl_xor_sync(0xffffffffu, acc, o);
        if (lane == 0) g_sel_tail[gw] = acc + B[ti];
    }
}

// ---------------- final NLL + mean -------------------------------------------
__global__ void final_kernel(const void* __restrict__ target, float* __restrict__ out)
{
    __shared__ float sh[NROWS];
    int r = threadIdx.x;
    int c = cluster_of(ld_target(target, r));
    float nll;
    if (c == 0)
        nll = g_head_lse[r] - g_sel_head[r];
    else
        nll = (g_head_lse[r] - g_sel_cluster[r]) + (g_tail_lse[r] - g_sel_tail[r]);
    sh[r] = nll;
    __syncthreads();
    for (int off = 512; off; off >>= 1) {
        if (r < off) sh[r] += sh[r + off];
        __syncthreads();
    }
    if (r == 0) out[0] = sh[0] * (1.0f / NROWS);
}

// ============================================================================
// launch
// ============================================================================
extern "C" void kernel_launch(void* const* d_in, const int* in_sizes, int n_in,
                              void* d_out, int out_size)
{
    const float* hidden = (const float*)d_in[0];
    const void*  target = d_in[1];                 // int32 or int64; detected on device
    const float* W0 = (const float*)d_in[2];
    const float* b0 = (const float*)d_in[3];
    const float* proj0 = (const float*)d_in[4];
    const float* W1 = (const float*)d_in[5];
    const float* b1 = (const float*)d_in[6];
    const float* proj1 = (const float*)d_in[7];
    const float* W2 = (const float*)d_in[8];
    const float* b2 = (const float*)d_in[9];
    const float* proj2 = (const float*)d_in[10];
    const float* W3 = (const float*)d_in[11];
    const float* b3 = (const float*)d_in[12];
    const float* proj3 = (const float*)d_in[13];
    const float* cW = (const float*)d_in[14];
    const float* cb = (const float*)d_in[15];
    float* out = (float*)d_out;

    void *vp0, *vp1, *vp2, *vp3, *vpm, *vps, *vhl, *vtl, *vrows, *vcnt;
    cudaGetSymbolAddress(&vp0, g_P0);
    cudaGetSymbolAddress(&vp1, g_P1);
    cudaGetSymbolAddress(&vp2, g_P2);
    cudaGetSymbolAddress(&vp3, g_P3);
    cudaGetSymbolAddress(&vpm, g_pm);
    cudaGetSymbolAddress(&vps, g_ps);
    cudaGetSymbolAddress(&vhl, g_head_lse);
    cudaGetSymbolAddress(&vtl, g_tail_lse);
    cudaGetSymbolAddress(&vrows, g_rows);
    cudaGetSymbolAddress(&vcnt, g_cnt);
    float* P0 = (float*)vp0;  float* P1 = (float*)vp1;
    float* P2 = (float*)vp2;  float* P3 = (float*)vp3;
    float* pm = (float*)vpm;  float* ps = (float*)vps;
    float* head_lse = (float*)vhl;  float* tail_lse = (float*)vtl;
    int* rows = (int*)vrows;  int* cnt = (int*)vcnt;

    detect_kernel<<<1, 256>>>((const int*)target);
    init_kernel<<<1, 32>>>();
    classify_kernel<<<4, 256>>>(target);

    // projections: P_i = hidden[1024,1024] @ proj_i[1024, d_i]
    gemm_kernel<false, false, false><<<dim3(8, 8), 256>>>(hidden, 1024, proj0, nullptr,
        nullptr, nullptr, 1024, 0, P0, 1024, nullptr, nullptr, nullptr, nullptr);
    gemm_kernel<false, false, false><<<dim3(2, 8), 256>>>(hidden, 1024, proj1, nullptr,
        nullptr, nullptr, 256, 0, P1, 256, nullptr, nullptr, nullptr, nullptr);
    gemm_kernel<false, false, false><<<dim3(1, 8), 256>>>(hidden, 1024, proj2, nullptr,
        nullptr, nullptr, 64, 0, P2, 64, nullptr, nullptr, nullptr, nullptr);
    gemm_kernel<false, false, false><<<dim3(1, 8), 256>>>(hidden, 1024, proj3, nullptr,
        nullptr, nullptr, 16, 0, P3, 16, nullptr, nullptr, nullptr, nullptr);

    // head: 20003 logits per row -> streaming LSE partials
    const int nblk_head = (20003 + TN - 1) / TN;   // 157
    gemm_kernel<true, true, true><<<dim3(nblk_head, 8), 256>>>(P0, 1024, W0, cW, b0, cb,
        20003, 20000, nullptr, 0, nullptr, nullptr, pm, ps);
    reduce_lse_kernel<<<NROWS, 128>>>(pm, ps, nblk_head, head_lse, nullptr, nullptr);

    // individual logits (target col / cluster cols / tail target col)
    sel_kernel<<<128, 256>>>(target, W0, b0, W1, b1, W2, b2, W3, b3, cW, cb);

    // tail cluster 1: V=20000, d=256
    {
        const int nblk = (20000 + TN - 1) / TN;    // 157
        gemm_kernel<true, true, false><<<dim3(nblk, 8), 256>>>(P1, 256, W1, nullptr, b1,
            nullptr, 20000, 0, nullptr, 0, rows + 0 * NROWS, cnt + 0, pm, ps);
        reduce_lse_kernel<<<NROWS, 128>>>(pm, ps, nblk, tail_lse, rows + 0 * NROWS, cnt + 0);
    }
    // tail cluster 2: V=160000, d=64
    {
        const int nblk = (160000 + TN - 1) / TN;   // 1250
        gemm_kernel<true, true, false><<<dim3(nblk, 8), 256>>>(P2, 64, W2, nullptr, b2,
            nullptr, 160000, 0, nullptr, 0, rows + 1 * NROWS, cnt + 1, pm, ps);
        reduce_lse_kernel<<<NROWS, 128>>>(pm, ps, nblk, tail_lse, rows + 1 * NROWS, cnt + 1);
    }
    // tail cluster 3: V=67735, d=16
    {
        const int nblk = (67735 + TN - 1) / TN;    // 530
        gemm_kernel<true, true, false><<<dim3(nblk, 8), 256>>>(P3, 16, W3, nullptr, b3,
            nullptr, 67735, 0, nullptr, 0, rows + 2 * NROWS, cnt + 2, pm, ps);
        reduce_lse_kernel<<<NROWS, 128>>>(pm, ps, nblk, tail_lse, rows + 2 * NROWS, cnt + 2);
    }

    final_kernel<<<1, NROWS>>>(target, out);
    (void)in_sizes; (void)n_in; (void)out_size;
}

// round 16
// speedup vs baseline: 1.0081x; 1.0007x over previous
#include <cuda_runtime.h>
#include <math.h>
#include <stdint.h>

// ============================================================================
// ProjectedAdaptiveLogSoftmax — fused adaptive softmax NLL (mean) on GB300
//
// Stages (all on one stream, graph-capturable, no allocations):
//   0. detect    : probe target dtype (int32 vs int64) -> g_is64 flag
//   1. init      : zero per-cluster row counters
//   2. classify  : compact row indices per tail cluster (atomics; result set
//                  is deterministic, per-row outputs are order-independent)
//   3. proj GEMM : P_i = hidden @ proj_i   (stored in __device__ scratch)
//   4. head GEMM : streaming (m, s) logsumexp partials over 20003 logits
//   5. reduce    : head LSE per row
//   6. sel       : the few individual logits needed (target col, cluster cols,
//                  tail target col) via one warp-dot per row
//   7. tail GEMMs: streaming LSE partials, gathered over compacted row lists
//   8. final     : per-row NLL, tree-reduced mean -> d_out[0]
// ============================================================================

#define NROWS   1024
#define DHID    1024
#define TM      128
#define TN      128
#define TK      8
#define PSTRIDE 1280   // >= ceil(160000/128) = 1250 partial blocks per row

#define CUT1 20000
#define CUT2 40000
#define CUT3 200000

// ------------------------- device scratch (static) -------------------------
static __device__ float g_P0[NROWS * 1024];
static __device__ float g_P1[NROWS * 256];
static __device__ float g_P2[NROWS * 64];
static __device__ float g_P3[NROWS * 16];
static __device__ float g_pm[NROWS * PSTRIDE];
static __device__ float g_ps[NROWS * PSTRIDE];
static __device__ float g_head_lse[NROWS];
static __device__ float g_tail_lse[NROWS];
static __device__ float g_sel_head[NROWS];
static __device__ float g_sel_cluster[NROWS];
static __device__ float g_sel_tail[NROWS];
static __device__ int   g_rows[3 * NROWS];
static __device__ int   g_cnt[3];
static __device__ int   g_is64;

// ------------------------------ helpers ------------------------------------
__device__ __forceinline__ int cluster_of(long long t) {
    return (t < CUT1) ? 0 : (t < CUT2) ? 1 : (t < CUT3) ? 2 : 3;
}

// dtype-agnostic target load (dispatches on runtime-detected width)
__device__ __forceinline__ long long ld_target(const void* p, int r) {
    if (g_is64) return ((const long long*)p)[r];
    return (long long)((const int*)p)[r];
}

// online logsumexp merge of (m1,s1) <- (m1,s1) + (m2,s2)
__device__ __forceinline__ void lse_combine(float& m, float& s, float m2, float s2) {
    float mn = fmaxf(m, m2);
    if (mn == -INFINITY) { m = mn; s = 0.f; return; }   // both empty
    s = s * __expf(m - mn) + s2 * __expf(m2 - mn);      // expf(-inf)=0, expf(0)=1
    m = mn;
}

// ---- dtype probe: view first 1024 int32 words (valid for either dtype).
// int64 targets (< 2^18) -> all 512 odd words are hi==0.
// int32 targets -> odd words are random values, ~surely nonzero somewhere.
__global__ void detect_kernel(const int* __restrict__ t32) {
    __shared__ int nz;
    if (threadIdx.x == 0) nz = 0;
    __syncthreads();
    for (int i = 2 * threadIdx.x + 1; i < NROWS; i += 2 * blockDim.x)
        if (t32[i] != 0) nz = 1;
    __syncthreads();
    if (threadIdx.x == 0) g_is64 = (nz == 0);
}

__global__ void init_kernel() {
    if (threadIdx.x < 3) g_cnt[threadIdx.x] = 0;
}

__global__ void classify_kernel(const void* __restrict__ target) {
    int r = blockIdx.x * blockDim.x + threadIdx.x;
    if (r >= NROWS) return;
    int c = cluster_of(ld_target(target, r));
    if (c > 0) {
        int p = atomicAdd(&g_cnt[c - 1], 1);
        g_rows[(c - 1) * NROWS + p] = r;
    }
}

// ============================================================================
// Tiled GEMM, fp32 with packed fma.rn.f32x2 (FFMA2) accumulation.
//   BNT  : B is [V, dK] row-major (weights; we need B^T)  vs [dK, V] (proj)
//   LSE  : emit per-(row, col-block) logsumexp partials    vs store C
//   HEAD : B is concat(W0[V0,dK], cluster_W[V-V0,dK]) with bias2 for tail cols
// Tile: 128x128 output, K-step 8, 256 threads, 8x8 micro-tile per thread.
// ============================================================================
template <bool BNT, bool LSE, bool HEAD>
__global__ __launch_bounds__(256, 2)
void gemm_kernel(const float* __restrict__ A, int dK,
                 const float* __restrict__ B, const float* __restrict__ B2,
                 const float* __restrict__ bias, const float* __restrict__ bias2,
                 int V, int V0,
                 float* __restrict__ C, int ldc,
                 const int* __restrict__ rowlist, const int* __restrict__ cntptr,
                 float* __restrict__ pm, float* __restrict__ ps)
{
    const int cnt  = cntptr ? *cntptr : NROWS;
    const int row0 = blockIdx.y * TM;
    if (rowlist && row0 >= cnt) return;           // dead row tile (tail clusters)
    const int col0 = blockIdx.x * TN;

    __shared__ int   rid[TM];
    __shared__ float As[TK][TM];
    __shared__ float Bs[TK][TN];

    const int tid = threadIdx.x;
    const int tx  = tid & 15;
    const int ty  = tid >> 4;

    if (tid < TM) {
        int pos  = row0 + tid;
        rid[tid] = rowlist ? (pos < cnt ? rowlist[pos] : 0) : pos;
    }

    // packed f32x2 accumulators: acc[i][j] holds cols (2j, 2j+1) of row i
    unsigned long long acc[8][4];
#pragma unroll
    for (int i = 0; i < 8; i++)
#pragma unroll
        for (int j = 0; j < 4; j++) acc[i][j] = 0ull;

    // per-thread load coords
    const int am = tid >> 1;            // 0..127 (row within tile)
    const int ak = (tid & 1) * 4;       // 0 or 4 (k within TK)
    const int pk = tid >> 5;            // proj-mode: k within TK (0..7)
    const int pn = (tid & 31) * 4;      // proj-mode: col within tile

    for (int k0 = 0; k0 < dK; k0 += TK) {
        __syncthreads();   // protect smem from previous iteration's readers (and rid)

        // ---- load A tile: As[k][m] = A[rid[m]][k0+k]
        {
            const float4 v = *(const float4*)(A + (size_t)rid[am] * dK + k0 + ak);
            As[ak + 0][am] = v.x; As[ak + 1][am] = v.y;
            As[ak + 2][am] = v.z; As[ak + 3][am] = v.w;
        }
        // ---- load B tile
        if (BNT) {          // Bs[k][n] = W[col0+n][k0+k]
            int cg = col0 + am;
            float4 v = make_float4(0.f, 0.f, 0.f, 0.f);
            if (HEAD) {
                if (cg < V0)      v = *(const float4*)(B  + (size_t)cg * dK + k0 + ak);
                else if (cg < V)  v = *(const float4*)(B2 + (size_t)(cg - V0) * dK + k0 + ak);
            } else {
                if (cg < V)       v = *(const float4*)(B  + (size_t)cg * dK + k0 + ak);
            }
            Bs[ak + 0][am] = v.x; Bs[ak + 1][am] = v.y;
            Bs[ak + 2][am] = v.z; Bs[ak + 3][am] = v.w;
        } else {            // Bs[k][n] = proj[k0+k][col0+n]  (contiguous in n)
            int cg = col0 + pn;
            float4 v = make_float4(0.f, 0.f, 0.f, 0.f);
            if (cg < V)  // V is a multiple of 4 for all projections
                v = *(const float4*)(B + (size_t)(k0 + pk) * V + cg);
            *(float4*)&Bs[pk][pn] = v;
        }
        __syncthreads();

        // ---- compute: 8x8 micro-tile, 32 FFMA2 per k
#pragma unroll
        for (int k = 0; k < TK; k++) {
            float a[8], b[8];
            *(float4*)(a)     = *(const float4*)&As[k][ty * 8];
            *(float4*)(a + 4) = *(const float4*)&As[k][ty * 8 + 4];
            *(float4*)(b)     = *(const float4*)&Bs[k][tx * 8];
            *(float4*)(b + 4) = *(const float4*)&Bs[k][tx * 8 + 4];

            unsigned long long av[8], bv[4];
#pragma unroll
            for (int i = 0; i < 8; i++)
                asm("mov.b64 %0, {%1, %1};" : "=l"(av[i]) : "f"(a[i]));
#pragma unroll
            for (int j = 0; j < 4; j++)
                asm("mov.b64 %0, {%1, %2};" : "=l"(bv[j]) : "f"(b[2 * j]), "f"(b[2 * j + 1]));
#pragma unroll
            for (int i = 0; i < 8; i++)
#pragma unroll
                for (int j = 0; j < 4; j++)
                    asm("fma.rn.f32x2 %0, %1, %2, %0;"
                        : "+l"(acc[i][j]) : "l"(av[i]), "l"(bv[j]));
        }
    }

    // unpack accumulators
    float accf[8][8];
#pragma unroll
    for (int i = 0; i < 8; i++)
#pragma unroll
        for (int j = 0; j < 4; j++)
            asm("mov.b64 {%0, %1}, %2;"
                : "=f"(accf[i][2 * j]), "=f"(accf[i][2 * j + 1]) : "l"(acc[i][j]));

    if (!LSE) {
        // store C (projection results); rows are identity here
#pragma unroll
        for (int i = 0; i < 8; i++) {
            int r = rid[ty * 8 + i];
#pragma unroll
            for (int j = 0; j < 8; j++) {
                int cg = col0 + tx * 8 + j;
                if (cg < V) C[(size_t)r * ldc + cg] = accf[i][j];
            }
        }
    } else {
        // add bias, mask OOB cols to -inf, per-row (m,s) over the 128-col tile
        const int cbase = col0 + tx * 8;
        float bj[8];
#pragma unroll
        for (int j = 0; j < 8; j++) {
            int cg = cbase + j;
            float bb = 0.f;
            if (cg < V) bb = (HEAD && cg >= V0) ? bias2[cg - V0] : bias[cg];
            bj[j] = bb;
        }
#pragma unroll
        for (int i = 0; i < 8; i++) {
            float m = -INFINITY;
            float v[8];
#pragma unroll
            for (int j = 0; j < 8; j++) {
                int cg = cbase + j;
                v[j] = (cg < V) ? (accf[i][j] + bj[j]) : -INFINITY;
                m = fmaxf(m, v[j]);
            }
            float s = 0.f;
            if (m > -INFINITY) {
#pragma unroll
                for (int j = 0; j < 8; j++) s += __expf(v[j] - m);
            }
            // reduce across the 16 lanes owning this row (xor<16 stays in group)
#pragma unroll
            for (int off = 8; off; off >>= 1) {
                float mo = __shfl_xor_sync(0xffffffffu, m, off);
                float so = __shfl_xor_sync(0xffffffffu, s, off);
                lse_combine(m, s, mo, so);
            }
            if (tx == 0) {
                int pidx = row0 + ty * 8 + i;   // list position (== row when identity)
                pm[(size_t)pidx * PSTRIDE + blockIdx.x] = m;
                ps[(size_t)pidx * PSTRIDE + blockIdx.x] = s;
            }
        }
    }
}

// ---------------- merge LSE partials per row --------------------------------
__global__ void reduce_lse_kernel(const float* __restrict__ pm, const float* __restrict__ ps,
                                  int nblk, float* __restrict__ out,
                                  const int* __restrict__ rowlist, const int* __restrict__ cntptr)
{
    int idx = blockIdx.x;
    if (cntptr && idx >= *cntptr) return;
    int tid = threadIdx.x;
    float m = -INFINITY, s = 0.f;
    for (int b = tid; b < nblk; b += 128)
        lse_combine(m, s, pm[(size_t)idx * PSTRIDE + b], ps[(size_t)idx * PSTRIDE + b]);
    __shared__ float sm[128], ss[128];
    sm[tid] = m; ss[tid] = s;
    __syncthreads();
    for (int off = 64; off; off >>= 1) {
        if (tid < off) {
            float mm = sm[tid], sv = ss[tid];
            lse_combine(mm, sv, sm[tid + off], ss[tid + off]);
            sm[tid] = mm; ss[tid] = sv;
        }
        __syncthreads();
    }
    if (tid == 0) {
        int row = rowlist ? rowlist[idx] : idx;
        out[row] = sm[0] + logf(ss[0]);
    }
}

// ---------------- selected logits: one warp per row --------------------------
__global__ void sel_kernel(const void* __restrict__ target,
                           const float* __restrict__ W0, const float* __restrict__ b0,
                           const float* __restrict__ W1, const float* __restrict__ b1,
                           const float* __restrict__ W2, const float* __restrict__ b2,
                           const float* __restrict__ W3, const float* __restrict__ b3,
                           const float* __restrict__ cW, const float* __restrict__ cb)
{
    int gw   = (blockIdx.x * blockDim.x + threadIdx.x) >> 5;
    int lane = threadIdx.x & 31;
    if (gw >= NROWS) return;
    long long t = ld_target(target, gw);
    int c = cluster_of(t);
    const float* p0 = g_P0 + (size_t)gw * 1024;

    // head token logit (t0 = clip(target, 0, 19999))
    {
        int colh = (int)(t < CUT1 ? t : (long long)(CUT1 - 1));
        const float* w = W0 + (size_t)colh * 1024;
        float acc = 0.f;
        for (int k = lane; k < 1024; k += 32) acc = fmaf(p0[k], w[k], acc);
#pragma unroll
        for (int o = 16; o; o >>= 1) acc += __shfl_xor_sync(0xffffffffu, acc, o);
        if (lane == 0) g_sel_head[gw] = acc + b0[colh];
    }
    if (c > 0) {
        // head cluster column: head_lp[:, -c] -> concat col (20003 - c) -> cluster_W[3-c]
        {
            const float* w = cW + (size_t)(3 - c) * 1024;
            float acc = 0.f;
            for (int k = lane; k < 1024; k += 32) acc = fmaf(p0[k], w[k], acc);
#pragma unroll
            for (int o = 16; o; o >>= 1) acc += __shfl_xor_sync(0xffffffffu, acc, o);
            if (lane == 0) g_sel_cluster[gw] = acc + cb[3 - c];
        }
        // tail token logit
        int lo = (c == 1) ? CUT1 : (c == 2) ? CUT2 : CUT3;
        int d  = (c == 1) ? 256  : (c == 2) ? 64   : 16;
        const float* P = (c == 1) ? g_P1 : (c == 2) ? g_P2 : g_P3;
        const float* W = (c == 1) ? W1 : (c == 2) ? W2 : W3;
        const float* B = (c == 1) ? b1 : (c == 2) ? b2 : b3;
        int ti = (int)(t - lo);
        const float* pr = P + (size_t)gw * d;
        const float* wr = W + (size_t)ti * d;
        float acc = 0.f;
        for (int k = lane; k < d; k += 32) acc = fmaf(pr[k], wr[k], acc);
#pragma unroll
        for (int o = 16; o; o >>= 1) acc += __shfl_xor_sync(0xffffffffu, acc, o);
        if (lane == 0) g_sel_tail[gw] = acc + B[ti];
    }
}

// ---------------- final NLL + mean -------------------------------------------
__global__ void final_kernel(const void* __restrict__ target, float* __restrict__ out)
{
    __shared__ float sh[NROWS];
    int r = threadIdx.x;
    int c = cluster_of(ld_target(target, r));
    float nll;
    if (c == 0)
        nll = g_head_lse[r] - g_sel_head[r];
    else
        nll = (g_head_lse[r] - g_sel_cluster[r]) + (g_tail_lse[r] - g_sel_tail[r]);
    sh[r] = nll;
    __syncthreads();
    for (int off = 512; off; off >>= 1) {
        if (r < off) sh[r] += sh[r + off];
        __syncthreads();
    }
    if (r == 0) out[0] = sh[0] * (1.0f / NROWS);
}

// ============================================================================
// launch
// ============================================================================
extern "C" void kernel_launch(void* const* d_in, const int* in_sizes, int n_in,
                              void* d_out, int out_size)
{
    const float* hidden = (const float*)d_in[0];
    const void*  target = d_in[1];                 // int32 or int64; detected on device
    const float* W0 = (const float*)d_in[2];
    const float* b0 = (const float*)d_in[3];
    const float* proj0 = (const float*)d_in[4];
    const float* W1 = (const float*)d_in[5];
    const float* b1 = (const float*)d_in[6];
    const float* proj1 = (const float*)d_in[7];
    const float* W2 = (const float*)d_in[8];
    const float* b2 = (const float*)d_in[9];
    const float* proj2 = (const float*)d_in[10];
    const float* W3 = (const float*)d_in[11];
    const float* b3 = (const float*)d_in[12];
    const float* proj3 = (const float*)d_in[13];
    const float* cW = (const float*)d_in[14];
    const float* cb = (const float*)d_in[15];
    float* out = (float*)d_out;

    void *vp0, *vp1, *vp2, *vp3, *vpm, *vps, *vhl, *vtl, *vrows, *vcnt;
    cudaGetSymbolAddress(&vp0, g_P0);
    cudaGetSymbolAddress(&vp1, g_P1);
    cudaGetSymbolAddress(&vp2, g_P2);
    cudaGetSymbolAddress(&vp3, g_P3);
    cudaGetSymbolAddress(&vpm, g_pm);
    cudaGetSymbolAddress(&vps, g_ps);
    cudaGetSymbolAddress(&vhl, g_head_lse);
    cudaGetSymbolAddress(&vtl, g_tail_lse);
    cudaGetSymbolAddress(&vrows, g_rows);
    cudaGetSymbolAddress(&vcnt, g_cnt);
    float* P0 = (float*)vp0;  float* P1 = (float*)vp1;
    float* P2 = (float*)vp2;  float* P3 = (float*)vp3;
    float* pm = (float*)vpm;  float* ps = (float*)vps;
    float* head_lse = (float*)vhl;  float* tail_lse = (float*)vtl;
    int* rows = (int*)vrows;  int* cnt = (int*)vcnt;

    detect_kernel<<<1, 256>>>((const int*)target);
    init_kernel<<<1, 32>>>();
    classify_kernel<<<4, 256>>>(target);

    // projections: P_i = hidden[1024,1024] @ proj_i[1024, d_i]
    gemm_kernel<false, false, false><<<dim3(8, 8), 256>>>(hidden, 1024, proj0, nullptr,
        nullptr, nullptr, 1024, 0, P0, 1024, nullptr, nullptr, nullptr, nullptr);
    gemm_kernel<false, false, false><<<dim3(2, 8), 256>>>(hidden, 1024, proj1, nullptr,
        nullptr, nullptr, 256, 0, P1, 256, nullptr, nullptr, nullptr, nullptr);
    gemm_kernel<false, false, false><<<dim3(1, 8), 256>>>(hidden, 1024, proj2, nullptr,
        nullptr, nullptr, 64, 0, P2, 64, nullptr, nullptr, nullptr, nullptr);
    gemm_kernel<false, false, false><<<dim3(1, 8), 256>>>(hidden, 1024, proj3, nullptr,
        nullptr, nullptr, 16, 0, P3, 16, nullptr, nullptr, nullptr, nullptr);

    // head: 20003 logits per row -> streaming LSE partials
    const int nblk_head = (20003 + TN - 1) / TN;   // 157
    gemm_kernel<true, true, true><<<dim3(nblk_head, 8), 256>>>(P0, 1024, W0, cW, b0, cb,
        20003, 20000, nullptr, 0, nullptr, nullptr, pm, ps);
    reduce_lse_kernel<<<NROWS, 128>>>(pm, ps, nblk_head, head_lse, nullptr, nullptr);

    // individual logits (target col / cluster cols / tail target col)
    sel_kernel<<<128, 256>>>(target, W0, b0, W1, b1, W2, b2, W3, b3, cW, cb);

    // tail cluster 1: V=20000, d=256
    {
        const int nblk = (20000 + TN - 1) / TN;    // 157
        gemm_kernel<true, true, false><<<dim3(nblk, 8), 256>>>(P1, 256, W1, nullptr, b1,
            nullptr, 20000, 0, nullptr, 0, rows + 0 * NROWS, cnt + 0, pm, ps);
        reduce_lse_kernel<<<NROWS, 128>>>(pm, ps, nblk, tail_lse, rows + 0 * NROWS, cnt + 0);
    }
    // tail cluster 2: V=160000, d=64
    {
        const int nblk = (160000 + TN - 1) / TN;   // 1250
        gemm_kernel<true, true, false><<<dim3(nblk, 8), 256>>>(P2, 64, W2, nullptr, b2,
            nullptr, 160000, 0, nullptr, 0, rows + 1 * NROWS, cnt + 1, pm, ps);
        reduce_lse_kernel<<<NROWS, 128>>>(pm, ps, nblk, tail_lse, rows + 1 * NROWS, cnt + 1);
    }
    // tail cluster 3: V=67735, d=16
    {
        const int nblk = (67735 + TN - 1) / TN;    // 530
        gemm_kernel<true, true, false><<<dim3(nblk, 8), 256>>>(P3, 16, W3, nullptr, b3,
            nullptr, 67735, 0, nullptr, 0, rows + 2 * NROWS, cnt + 2, pm, ps);
        reduce_lse_kernel<<<NROWS, 128>>>(pm, ps, nblk, tail_lse, rows + 2 * NROWS, cnt + 2);
    }

    final_kernel<<<1, NROWS>>>(target, out);
    (void)in_sizes; (void)n_in; (void)out_size;
}